// round 8
// baseline (speedup 1.0000x reference)
#include <cuda_runtime.h>
#include <math.h>
#include <stdint.h>

#define HID     64
#define TWO_H   128
#define TILE    128
#define NTHR    256
#define EPSF    1e-5f
#define SLOPEF  0.2f

#define WPS     68     // packed weight row stride (uint2 units): banks 4q+grp conflict-free
#define APS     68     // packed activation row stride (uint2 units): banks 4grp+q conflict-free
#define MSS     68     // message staging row stride (floats)

// shared memory layout (float offsets)
#define OFF_W1P 0        // 64 rows * 68 uint2 = 8704 floats ; AP/MS overlay after GEMM1
#define OFF_W2P 8704     // 32 rows * 68 uint2 = 4352 floats
#define OFF_W3P 13056    // 4352 floats
#define OFF_HP  17408    // 64 rows * 68 uint2 = 8704 floats
#define OFF_G1  26112
#define OFF_B1  26240
#define OFF_G2  26368
#define OFF_B2  26432
#define OFF_G3  26496
#define OFF_B3  26560
#define OFF_EW  26624
#define OFF_TGT 26752
#define SMEM_FLOATS 26880
#define SMEM_BYTES  (SMEM_FLOATS * 4)   // 107,520 B -> 2 blocks/SM

// -------- sort scratch (device globals; no runtime allocation) --------
#define MAXN 262145
#define MAXE 1048576
#define SCAN_CHUNK 4096
#define MAXCHUNK 128
__device__ int d_cnt[MAXN + 1];
__device__ int d_sorted[MAXE];
__device__ int d_scan_flag[MAXCHUNK];
__device__ int d_scan_agg[MAXCHUNK];
__device__ int d_scan_inc[MAXCHUNK];
__device__ int d_scan_ticket;

// monotone float->uint transform
__device__ __forceinline__ unsigned fkey(float v) {
    unsigned u = __float_as_uint(v);
    return u ^ (unsigned)(((int)u >> 31) | 0x80000000);
}
#define KEY_NEG_INF 0x007FFFFFu
#define NEG_INF_F   __int_as_float(0xFF800000)

__device__ __forceinline__ uint32_t f2tf32(float f) {
    uint32_t r;
    asm("cvt.rna.tf32.f32 %0, %1;" : "=r"(r) : "f"(f));
    return r;
}

__device__ __forceinline__ void mma_tf32(float acc[4],
                                         uint32_t a0, uint32_t a1, uint32_t a2, uint32_t a3,
                                         uint32_t b0, uint32_t b1) {
    asm volatile(
        "mma.sync.aligned.m16n8k8.row.col.f32.tf32.tf32.f32 "
        "{%0,%1,%2,%3}, {%4,%5,%6,%7}, {%8,%9}, {%0,%1,%2,%3};"
        : "+f"(acc[0]), "+f"(acc[1]), "+f"(acc[2]), "+f"(acc[3])
        : "r"(a0), "r"(a1), "r"(a2), "r"(a3), "r"(b0), "r"(b1));
}

// ======================= prep kernels =======================
__global__ void zero_kernel(int n) {
    int i = blockIdx.x * blockDim.x + threadIdx.x;
    if (i < n) d_cnt[i] = 0;
    if (i < MAXCHUNK) d_scan_flag[i] = 0;
    if (i == MAXCHUNK) d_scan_ticket = 0;
}

__global__ void init_kernel(uint4* __restrict__ out, int n4) {
    int i = blockIdx.x * blockDim.x + threadIdx.x;
    if (i < n4) out[i] = make_uint4(KEY_NEG_INF, KEY_NEG_INF, KEY_NEG_INF, KEY_NEG_INF);
}

__global__ void hist_kernel(const int* __restrict__ eindex, int E) {
    int i = blockIdx.x * blockDim.x + threadIdx.x;
    if (i < E) atomicAdd(&d_cnt[eindex[E + i] + 1], 1);
}

// single-pass inclusive scan of d_cnt[0..n) with decoupled lookback
__global__ void scan_lb_kernel(int n) {
    __shared__ int sbid;
    __shared__ int warp_tot[8];
    __shared__ int excl_sh;
    const int t = threadIdx.x, lane = t & 31, w = t >> 5;

    if (t == 0) sbid = atomicAdd(&d_scan_ticket, 1);
    __syncthreads();
    const int bid  = sbid;
    const int base = bid * SCAN_CHUNK + t * 16;

    int v[16];
    if (base + 15 < n) {
        #pragma unroll
        for (int j = 0; j < 4; j++) {
            int4 qv = *(const int4*)(d_cnt + base + 4 * j);
            v[4*j] = qv.x; v[4*j+1] = qv.y; v[4*j+2] = qv.z; v[4*j+3] = qv.w;
        }
    } else {
        #pragma unroll
        for (int j = 0; j < 16; j++) v[j] = (base + j < n) ? d_cnt[base + j] : 0;
    }
    #pragma unroll
    for (int j = 1; j < 16; j++) v[j] += v[j - 1];

    int s = v[15];
    #pragma unroll
    for (int o = 1; o < 32; o <<= 1) {
        int u = __shfl_up_sync(0xffffffffu, s, o);
        if (lane >= o) s += u;
    }
    if (lane == 31) warp_tot[w] = s;
    __syncthreads();
    if (w == 0) {
        int ws = (lane < 8) ? warp_tot[lane] : 0;
        #pragma unroll
        for (int o = 1; o < 8; o <<= 1) {
            int u = __shfl_up_sync(0xffffffffu, ws, o);
            if (lane >= o) ws += u;
        }
        if (lane < 8) warp_tot[lane] = ws;
    }
    __syncthreads();
    const int block_tot = warp_tot[7];
    const int thr_excl  = (s - v[15]) + (w > 0 ? warp_tot[w - 1] : 0);

    if (t == 0) {
        d_scan_agg[bid] = block_tot;
        __threadfence();
        atomicExch(&d_scan_flag[bid], 1);
        int excl = 0;
        for (int p = bid - 1; p >= 0; ) {
            int f;
            do { f = atomicAdd(&d_scan_flag[p], 0); } while (f == 0);
            if (f == 2) { excl += atomicAdd(&d_scan_inc[p], 0); break; }
            excl += atomicAdd(&d_scan_agg[p], 0);
            p--;
        }
        d_scan_inc[bid] = excl + block_tot;
        __threadfence();
        atomicExch(&d_scan_flag[bid], 2);
        excl_sh = excl;
    }
    __syncthreads();
    const int add = excl_sh + thr_excl;

    if (base + 15 < n) {
        #pragma unroll
        for (int j = 0; j < 4; j++) {
            int4 qv; qv.x = v[4*j] + add; qv.y = v[4*j+1] + add; qv.z = v[4*j+2] + add; qv.w = v[4*j+3] + add;
            *(int4*)(d_cnt + base + 4 * j) = qv;
        }
    } else {
        #pragma unroll
        for (int j = 0; j < 16; j++) if (base + j < n) d_cnt[base + j] = v[j] + add;
    }
}

__global__ void scatter_kernel(const int* __restrict__ eindex, int E) {
    int i = blockIdx.x * blockDim.x + threadIdx.x;
    if (i < E) {
        int tg = eindex[E + i];
        int pos = atomicAdd(&d_cnt[tg], 1);
        d_sorted[pos] = i;
    }
}

__global__ void finalize_kernel(const float* __restrict__ x, float* __restrict__ out, int n) {
    int i = blockIdx.x * blockDim.x + threadIdx.x;
    if (i < n) {
        unsigned u = ((const unsigned*)out)[i];
        unsigned bits = (u & 0x80000000u) ? (u ^ 0x80000000u) : ~u;
        float v = __uint_as_float(bits);
        if (isinf(v)) v = 0.0f;
        out[i] = v + x[i];
    }
}

// ======================= main edge kernel =======================
__global__ void __launch_bounds__(NTHR, 2)
edge_kernel(const float* __restrict__ x,
            const float* __restrict__ eweight,
            const int* __restrict__ eindex,
            const float* __restrict__ w1,
            const float* __restrict__ w2,
            const float* __restrict__ w3,
            const float* __restrict__ g1, const float* __restrict__ b1,
            const float* __restrict__ g2, const float* __restrict__ b2,
            const float* __restrict__ g3, const float* __restrict__ b3,
            float* __restrict__ out, int E)
{
    extern __shared__ float sm[];
    uint2* w1p = (uint2*)(sm + OFF_W1P);
    uint2* w2p = (uint2*)(sm + OFF_W2P);
    uint2* w3p = (uint2*)(sm + OFF_W3P);
    uint2* AP  = (uint2*)(sm + OFF_W1P);   // overlays w1p after GEMM1
    uint2* HP  = (uint2*)(sm + OFF_HP);
    float* MS  = sm + OFF_W1P;             // overlays AP for epilogue staging
    float* g1s = sm + OFF_G1;
    float* b1s = sm + OFF_B1;
    float* g2s = sm + OFF_G2;
    float* b2s = sm + OFF_B2;
    float* g3s = sm + OFF_G3;
    float* b3s = sm + OFF_B3;
    float* ews = sm + OFF_EW;
    int*   tgts = (int*)(sm + OFF_TGT);

    const int t    = threadIdx.x;
    const int lane = t & 31;
    const int wid  = t >> 5;          // 0..7
    const int e0   = blockIdx.x * TILE;

    // ---- stage packed weights: wp[(kt*4+q)*WPS + c] = {w[8kt+q][c], w[8kt+4+q][c]} (tf32) ----
    for (int i = t; i < 1024; i += NTHR) {            // w1: 16 kt x 64 c
        int kt = i >> 6, c = i & 63;
        float4 va = *(const float4*)(w1 + c * TWO_H + kt * 8);
        float4 vb = *(const float4*)(w1 + c * TWO_H + kt * 8 + 4);
        w1p[(kt*4 + 0) * WPS + c] = make_uint2(f2tf32(va.x), f2tf32(vb.x));
        w1p[(kt*4 + 1) * WPS + c] = make_uint2(f2tf32(va.y), f2tf32(vb.y));
        w1p[(kt*4 + 2) * WPS + c] = make_uint2(f2tf32(va.z), f2tf32(vb.z));
        w1p[(kt*4 + 3) * WPS + c] = make_uint2(f2tf32(va.w), f2tf32(vb.w));
    }
    for (int i = t; i < 512; i += NTHR) {             // w2, w3: 8 kt x 64 c
        int kt = i >> 6, c = i & 63;
        float4 va2 = *(const float4*)(w2 + c * HID + kt * 8);
        float4 vb2 = *(const float4*)(w2 + c * HID + kt * 8 + 4);
        float4 va3 = *(const float4*)(w3 + c * HID + kt * 8);
        float4 vb3 = *(const float4*)(w3 + c * HID + kt * 8 + 4);
        w2p[(kt*4 + 0) * WPS + c] = make_uint2(f2tf32(va2.x), f2tf32(vb2.x));
        w2p[(kt*4 + 1) * WPS + c] = make_uint2(f2tf32(va2.y), f2tf32(vb2.y));
        w2p[(kt*4 + 2) * WPS + c] = make_uint2(f2tf32(va2.z), f2tf32(vb2.z));
        w2p[(kt*4 + 3) * WPS + c] = make_uint2(f2tf32(va2.w), f2tf32(vb2.w));
        w3p[(kt*4 + 0) * WPS + c] = make_uint2(f2tf32(va3.x), f2tf32(vb3.x));
        w3p[(kt*4 + 1) * WPS + c] = make_uint2(f2tf32(va3.y), f2tf32(vb3.y));
        w3p[(kt*4 + 2) * WPS + c] = make_uint2(f2tf32(va3.z), f2tf32(vb3.z));
        w3p[(kt*4 + 3) * WPS + c] = make_uint2(f2tf32(va3.w), f2tf32(vb3.w));
    }
    if (t < 128) { g1s[t] = g1[t]; b1s[t] = b1[t]; }
    else if (t < 192) {
        int u = t - 128;
        g2s[u] = g2[u]; b2s[u] = b2[u]; g3s[u] = g3[u]; b3s[u] = b3[u];
    }
    if (t < TILE) {
        int ge = e0 + t;
        int eid = (ge < E) ? d_sorted[ge] : -1;
        if (eid >= 0) {
            tgts[t] = eindex[E + eid];
            ews[t]  = eweight[eid];
        } else {
            tgts[t] = -1;
            ews[t]  = 0.0f;
        }
    }
    __syncthreads();

    const int grp  = lane >> 2;     // 0..7
    const int q    = lane & 3;      // 0..3
    const int r_lo = wid * 16 + grp;
    const int r_hi = r_lo + 8;
    const int rp   = wid * 8 + grp; // packed row-pair index

    // ---- gather m-fragments straight into registers ----
    float mlo[32], mhi[32];
    {
        int ge = e0 + r_lo;
        if (ge < E && tgts[r_lo] >= 0) {
            int eid = d_sorted[ge];
            const float* xi = x + (size_t)tgts[r_lo] * HID;
            const float* xj = x + (size_t)eindex[eid] * HID;
            float w = ews[r_lo];
            #pragma unroll
            for (int tt = 0; tt < 16; tt++) {
                int c = q + 4 * tt;
                float vi = __ldg(xi + c);
                float vj = __ldg(xj + c);
                mlo[tt]      = vi;
                mlo[16 + tt] = w * (vj - vi);
            }
        } else {
            #pragma unroll
            for (int tt = 0; tt < 32; tt++) mlo[tt] = 0.0f;
        }
    }
    {
        int ge = e0 + r_hi;
        if (ge < E && tgts[r_hi] >= 0) {
            int eid = d_sorted[ge];
            const float* xi = x + (size_t)tgts[r_hi] * HID;
            const float* xj = x + (size_t)eindex[eid] * HID;
            float w = ews[r_hi];
            #pragma unroll
            for (int tt = 0; tt < 16; tt++) {
                int c = q + 4 * tt;
                float vi = __ldg(xi + c);
                float vj = __ldg(xj + c);
                mhi[tt]      = vi;
                mhi[16 + tt] = w * (vj - vi);
            }
        } else {
            #pragma unroll
            for (int tt = 0; tt < 32; tt++) mhi[tt] = 0.0f;
        }
    }

    // ---- LN1 (width 128) in registers ----
    {
        float s_lo = 0.f, q_lo = 0.f, s_hi = 0.f, q_hi = 0.f;
        #pragma unroll
        for (int tt = 0; tt < 32; tt++) {
            s_lo += mlo[tt]; q_lo += mlo[tt] * mlo[tt];
            s_hi += mhi[tt]; q_hi += mhi[tt] * mhi[tt];
        }
        #pragma unroll
        for (int o = 1; o <= 2; o <<= 1) {
            s_lo += __shfl_xor_sync(0xffffffffu, s_lo, o);
            q_lo += __shfl_xor_sync(0xffffffffu, q_lo, o);
            s_hi += __shfl_xor_sync(0xffffffffu, s_hi, o);
            q_hi += __shfl_xor_sync(0xffffffffu, q_hi, o);
        }
        float mu_lo = s_lo * (1.0f / 128.0f);
        float mu_hi = s_hi * (1.0f / 128.0f);
        float r_l   = rsqrtf(fmaxf(q_lo * (1.0f / 128.0f) - mu_lo * mu_lo, 0.0f) + EPSF);
        float r_h   = rsqrtf(fmaxf(q_hi * (1.0f / 128.0f) - mu_hi * mu_hi, 0.0f) + EPSF);
        #pragma unroll
        for (int tt = 0; tt < 32; tt++) {
            int c = q + 4 * tt;
            float g = g1s[c], b = b1s[c];
            float h0 = (mlo[tt] - mu_lo) * r_l * g + b;
            float h1 = (mhi[tt] - mu_hi) * r_h * g + b;
            h0 = h0 > 0.f ? h0 : SLOPEF * h0;
            h1 = h1 > 0.f ? h1 : SLOPEF * h1;
            mlo[tt] = __uint_as_float(f2tf32(h0));
            mhi[tt] = __uint_as_float(f2tf32(h1));
        }
    }

    float acc[8][4];

    // ================= GEMM1 (A regs, B packed LDS.64) =================
    #pragma unroll
    for (int nt = 0; nt < 8; nt++)
        #pragma unroll
        for (int j = 0; j < 4; j++) acc[nt][j] = 0.0f;
    #pragma unroll
    for (int kt = 0; kt < 16; kt++) {
        uint32_t a0 = __float_as_uint(mlo[2 * kt]);
        uint32_t a1 = __float_as_uint(mhi[2 * kt]);
        uint32_t a2 = __float_as_uint(mlo[2 * kt + 1]);
        uint32_t a3 = __float_as_uint(mhi[2 * kt + 1]);
        const uint2* wrow = w1p + (kt * 4 + q) * WPS + grp;
        #pragma unroll
        for (int nt = 0; nt < 8; nt++) {
            uint2 bb = wrow[nt * 8];
            mma_tf32(acc[nt], a0, a1, a2, a3, bb.x, bb.y);
        }
    }

    // ---- LN2 in registers, packed STS.128 into AP (overlays w1p) ----
    {
        float s_lo = 0.f, q_lo = 0.f, s_hi = 0.f, q_hi = 0.f;
        #pragma unroll
        for (int nt = 0; nt < 8; nt++) {
            s_lo += acc[nt][0] + acc[nt][1];
            q_lo += acc[nt][0]*acc[nt][0] + acc[nt][1]*acc[nt][1];
            s_hi += acc[nt][2] + acc[nt][3];
            q_hi += acc[nt][2]*acc[nt][2] + acc[nt][3]*acc[nt][3];
        }
        #pragma unroll
        for (int o = 1; o <= 2; o <<= 1) {
            s_lo += __shfl_xor_sync(0xffffffffu, s_lo, o);
            q_lo += __shfl_xor_sync(0xffffffffu, q_lo, o);
            s_hi += __shfl_xor_sync(0xffffffffu, s_hi, o);
            q_hi += __shfl_xor_sync(0xffffffffu, q_hi, o);
        }
        float mu_lo = s_lo * (1.0f/64.0f);
        float mu_hi = s_hi * (1.0f/64.0f);
        float r_l   = rsqrtf(fmaxf(q_lo * (1.0f/64.0f) - mu_lo*mu_lo, 0.0f) + EPSF);
        float r_h   = rsqrtf(fmaxf(q_hi * (1.0f/64.0f) - mu_hi*mu_hi, 0.0f) + EPSF);

        __syncthreads();   // all warps done reading w1p before AP overlays it
        #pragma unroll
        for (int nt = 0; nt < 8; nt++) {
            int c0 = nt * 8 + 2 * q;
            float2 g = *(float2*)(g2s + c0);
            float2 b = *(float2*)(b2s + c0);
            float h0 = (acc[nt][0] - mu_lo) * r_l * g.x + b.x;
            float h1 = (acc[nt][1] - mu_lo) * r_l * g.y + b.y;
            float h2 = (acc[nt][2] - mu_hi) * r_h * g.x + b.x;
            float h3 = (acc[nt][3] - mu_hi) * r_h * g.y + b.y;
            h0 = h0 > 0.f ? h0 : SLOPEF * h0;
            h1 = h1 > 0.f ? h1 : SLOPEF * h1;
            h2 = h2 > 0.f ? h2 : SLOPEF * h2;
            h3 = h3 > 0.f ? h3 : SLOPEF * h3;
            // AP[rp*APS + c] = {A[r][c], A[r+8][c]} ; uint4 = two adjacent uint2
            uint4 pk = make_uint4(f2tf32(h0), f2tf32(h2), f2tf32(h1), f2tf32(h3));
            *(uint4*)(AP + rp * APS + c0) = pk;
        }
    }
    __syncwarp();

    // ================= GEMM2 (A packed LDS.64, B packed LDS.64) =================
    #pragma unroll
    for (int nt = 0; nt < 8; nt++)
        #pragma unroll
        for (int j = 0; j < 4; j++) acc[nt][j] = 0.0f;
    {
        const uint2* Ab = AP + rp * APS;
        #pragma unroll
        for (int kt = 0; kt < 8; kt++) {
            uint2 lo = Ab[kt * 8 + q];        // a0, a1
            uint2 hi = Ab[kt * 8 + 4 + q];    // a2, a3
            const uint2* wrow = w2p + (kt * 4 + q) * WPS + grp;
            #pragma unroll
            for (int nt = 0; nt < 8; nt++) {
                uint2 bb = wrow[nt * 8];
                mma_tf32(acc[nt], lo.x, lo.y, hi.x, hi.y, bb.x, bb.y);
            }
        }
    }

    // ---- LN3 in registers, packed STS.128 into HP ----
    {
        float s_lo = 0.f, q_lo = 0.f, s_hi = 0.f, q_hi = 0.f;
        #pragma unroll
        for (int nt = 0; nt < 8; nt++) {
            s_lo += acc[nt][0] + acc[nt][1];
            q_lo += acc[nt][0]*acc[nt][0] + acc[nt][1]*acc[nt][1];
            s_hi += acc[nt][2] + acc[nt][3];
            q_hi += acc[nt][2]*acc[nt][2] + acc[nt][3]*acc[nt][3];
        }
        #pragma unroll
        for (int o = 1; o <= 2; o <<= 1) {
            s_lo += __shfl_xor_sync(0xffffffffu, s_lo, o);
            q_lo += __shfl_xor_sync(0xffffffffu, q_lo, o);
            s_hi += __shfl_xor_sync(0xffffffffu, s_hi, o);
            q_hi += __shfl_xor_sync(0xffffffffu, q_hi, o);
        }
        float mu_lo = s_lo * (1.0f/64.0f);
        float mu_hi = s_hi * (1.0f/64.0f);
        float r_l   = rsqrtf(fmaxf(q_lo * (1.0f/64.0f) - mu_lo*mu_lo, 0.0f) + EPSF);
        float r_h   = rsqrtf(fmaxf(q_hi * (1.0f/64.0f) - mu_hi*mu_hi, 0.0f) + EPSF);

        #pragma unroll
        for (int nt = 0; nt < 8; nt++) {
            int c0 = nt * 8 + 2 * q;
            float2 g = *(float2*)(g3s + c0);
            float2 b = *(float2*)(b3s + c0);
            float h0 = (acc[nt][0] - mu_lo) * r_l * g.x + b.x;
            float h1 = (acc[nt][1] - mu_lo) * r_l * g.y + b.y;
            float h2 = (acc[nt][2] - mu_hi) * r_h * g.x + b.x;
            float h3 = (acc[nt][3] - mu_hi) * r_h * g.y + b.y;
            h0 = h0 > 0.f ? h0 : SLOPEF * h0;
            h1 = h1 > 0.f ? h1 : SLOPEF * h1;
            h2 = h2 > 0.f ? h2 : SLOPEF * h2;
            h3 = h3 > 0.f ? h3 : SLOPEF * h3;
            uint4 pk = make_uint4(f2tf32(h0), f2tf32(h2), f2tf32(h1), f2tf32(h3));
            *(uint4*)(HP + rp * APS + c0) = pk;
        }
    }
    __syncwarp();

    // ================= GEMM3 (A packed from HP) =================
    #pragma unroll
    for (int nt = 0; nt < 8; nt++)
        #pragma unroll
        for (int j = 0; j < 4; j++) acc[nt][j] = 0.0f;
    {
        const uint2* Ab = HP + rp * APS;
        #pragma unroll
        for (int kt = 0; kt < 8; kt++) {
            uint2 lo = Ab[kt * 8 + q];
            uint2 hi = Ab[kt * 8 + 4 + q];
            const uint2* wrow = w3p + (kt * 4 + q) * WPS + grp;
            #pragma unroll
            for (int nt = 0; nt < 8; nt++) {
                uint2 bb = wrow[nt * 8];
                mma_tf32(acc[nt], lo.x, lo.y, hi.x, hi.y, bb.x, bb.y);
            }
        }
    }
    // stage raw messages into MS (overlays AP; same warp-private float range)
    #pragma unroll
    for (int nt = 0; nt < 8; nt++) {
        int c0 = nt * 8 + 2 * q;
        float* o = MS + r_lo * MSS + c0;
        *(float2*)o             = make_float2(acc[nt][0], acc[nt][1]);
        *(float2*)(o + 8 * MSS) = make_float2(acc[nt][2], acc[nt][3]);
    }
    __syncthreads();

    // ---- run-aggregated segment-max epilogue ----
    {
        unsigned* outu = (unsigned*)out;
        const int c  = t & 63;
        const int gi = t >> 6;
        const int rs = gi * 32;
        float m = NEG_INF_F;
        int cur = tgts[rs];
        #pragma unroll 4
        for (int r = rs; r < rs + 32; r++) {
            int tg = tgts[r];
            if (tg != cur) {
                if (cur >= 0) atomicMax(outu + (unsigned)cur * HID + c, fkey(m));
                cur = tg;
                m = NEG_INF_F;
            }
            m = fmaxf(m, MS[r * MSS + c]);
        }
        if (cur >= 0) atomicMax(outu + (unsigned)cur * HID + c, fkey(m));
    }
}

extern "C" void kernel_launch(void* const* d_in, const int* in_sizes, int n_in,
                              void* d_out, int out_size) {
    const float* x  = (const float*)d_in[0];
    const float* ew = (const float*)d_in[1];
    const int*   ei = (const int*)d_in[2];
    const float* w1 = (const float*)d_in[3];
    const float* w2 = (const float*)d_in[4];
    const float* w3 = (const float*)d_in[5];
    const float* g1 = (const float*)d_in[6];
    const float* b1 = (const float*)d_in[7];
    const float* g2 = (const float*)d_in[8];
    const float* b2 = (const float*)d_in[9];
    const float* g3 = (const float*)d_in[10];
    const float* b3 = (const float*)d_in[11];
    float* out = (float*)d_out;

    const int E  = in_sizes[1];
    const int NH = out_size;
    const int N  = NH / HID;
    const int n  = N + 1;
    const int nchunk = (n + SCAN_CHUNK - 1) / SCAN_CHUNK;

    cudaFuncSetAttribute(edge_kernel, cudaFuncAttributeMaxDynamicSharedMemorySize, SMEM_BYTES);

    zero_kernel<<<(n + 255) / 256, 256>>>(n);
    init_kernel<<<(NH / 4 + 255) / 256, 256>>>((uint4*)out, NH / 4);
    hist_kernel<<<(E + 255) / 256, 256>>>(ei, E);
    scan_lb_kernel<<<nchunk, 256>>>(n);
    scatter_kernel<<<(E + 255) / 256, 256>>>(ei, E);
    edge_kernel<<<(E + TILE - 1) / TILE, NTHR, SMEM_BYTES>>>(
        x, ew, ei, w1, w2, w3, g1, b1, g2, b2, g3, b3, out, E);
    finalize_kernel<<<(NH + 255) / 256, 256>>>(x, out, NH);
}

// round 9
// speedup vs baseline: 1.3266x; 1.3266x over previous
#include <cuda_runtime.h>
#include <math.h>
#include <stdint.h>

#define HID     64
#define TWO_H   128
#define TILE    128
#define NTHR    256
#define EPSF    1e-5f
#define SLOPEF  0.2f

#define WPS     68     // packed weight row stride (uint2 units)
#define APS     68     // packed activation row stride (uint2 units)
#define MSS     68     // message staging row stride (floats)

// shared memory layout (float offsets)
#define OFF_W1P 0        // 8704 (persists whole kernel)
#define OFF_W2P 8704     // 4352
#define OFF_W3P 13056    // 4352
#define OFF_AB  17408    // 8704: AP/HP/MS all overlay here (warp-private rows)
#define OFF_G1  26112
#define OFF_B1  26240
#define OFF_G2  26368
#define OFF_B2  26432
#define OFF_G3  26496
#define OFF_B3  26560
#define OFF_TG0 26624
#define OFF_TG1 26752
#define OFF_SR0 26880
#define OFF_SR1 27008
#define OFF_EW0 27136
#define OFF_EW1 27264
#define SMEM_FLOATS 27392
#define SMEM_BYTES  (SMEM_FLOATS * 4)   // 109,568 B -> 2 blocks/SM

// -------- sort scratch --------
#define MAXN 262145
#define MAXE 1048576
#define SCAN_CHUNK 4096
#define MAXCHUNK 128
__device__ int d_cnt[MAXN + 1];
__device__ int d_sorted[MAXE];
__device__ int d_scan_flag[MAXCHUNK];
__device__ int d_scan_agg[MAXCHUNK];
__device__ int d_scan_inc[MAXCHUNK];
__device__ int d_scan_ticket;

__device__ __forceinline__ unsigned fkey(float v) {
    unsigned u = __float_as_uint(v);
    return u ^ (unsigned)(((int)u >> 31) | 0x80000000);
}
#define KEY_NEG_INF 0x007FFFFFu
#define NEG_INF_F   __int_as_float(0xFF800000)

__device__ __forceinline__ uint32_t f2tf32(float f) {
    uint32_t r;
    asm("cvt.rna.tf32.f32 %0, %1;" : "=r"(r) : "f"(f));
    return r;
}

__device__ __forceinline__ void mma_tf32(float acc[4],
                                         uint32_t a0, uint32_t a1, uint32_t a2, uint32_t a3,
                                         uint32_t b0, uint32_t b1) {
    asm volatile(
        "mma.sync.aligned.m16n8k8.row.col.f32.tf32.tf32.f32 "
        "{%0,%1,%2,%3}, {%4,%5,%6,%7}, {%8,%9}, {%0,%1,%2,%3};"
        : "+f"(acc[0]), "+f"(acc[1]), "+f"(acc[2]), "+f"(acc[3])
        : "r"(a0), "r"(a1), "r"(a2), "r"(a3), "r"(b0), "r"(b1));
}

// ======================= prep kernels =======================
__global__ void zero_init_kernel(int n, uint4* __restrict__ out, int n4) {
    int i = blockIdx.x * blockDim.x + threadIdx.x;
    if (i < n) d_cnt[i] = 0;
    if (i < MAXCHUNK) d_scan_flag[i] = 0;
    if (i == MAXCHUNK) d_scan_ticket = 0;
    if (i < n4) out[i] = make_uint4(KEY_NEG_INF, KEY_NEG_INF, KEY_NEG_INF, KEY_NEG_INF);
}

__global__ void hist_kernel(const int* __restrict__ eindex, int E) {
    int i = blockIdx.x * blockDim.x + threadIdx.x;
    if (i < E) atomicAdd(&d_cnt[eindex[E + i] + 1], 1);
}

__global__ void scan_lb_kernel(int n) {
    __shared__ int sbid;
    __shared__ int warp_tot[8];
    __shared__ int excl_sh;
    const int t = threadIdx.x, lane = t & 31, w = t >> 5;

    if (t == 0) sbid = atomicAdd(&d_scan_ticket, 1);
    __syncthreads();
    const int bid  = sbid;
    const int base = bid * SCAN_CHUNK + t * 16;

    int v[16];
    if (base + 15 < n) {
        #pragma unroll
        for (int j = 0; j < 4; j++) {
            int4 qv = *(const int4*)(d_cnt + base + 4 * j);
            v[4*j] = qv.x; v[4*j+1] = qv.y; v[4*j+2] = qv.z; v[4*j+3] = qv.w;
        }
    } else {
        #pragma unroll
        for (int j = 0; j < 16; j++) v[j] = (base + j < n) ? d_cnt[base + j] : 0;
    }
    #pragma unroll
    for (int j = 1; j < 16; j++) v[j] += v[j - 1];

    int s = v[15];
    #pragma unroll
    for (int o = 1; o < 32; o <<= 1) {
        int u = __shfl_up_sync(0xffffffffu, s, o);
        if (lane >= o) s += u;
    }
    if (lane == 31) warp_tot[w] = s;
    __syncthreads();
    if (w == 0) {
        int ws = (lane < 8) ? warp_tot[lane] : 0;
        #pragma unroll
        for (int o = 1; o < 8; o <<= 1) {
            int u = __shfl_up_sync(0xffffffffu, ws, o);
            if (lane >= o) ws += u;
        }
        if (lane < 8) warp_tot[lane] = ws;
    }
    __syncthreads();
    const int block_tot = warp_tot[7];
    const int thr_excl  = (s - v[15]) + (w > 0 ? warp_tot[w - 1] : 0);

    if (t == 0) {
        d_scan_agg[bid] = block_tot;
        __threadfence();
        atomicExch(&d_scan_flag[bid], 1);
        int excl = 0;
        for (int p = bid - 1; p >= 0; ) {
            int f;
            do { f = atomicAdd(&d_scan_flag[p], 0); } while (f == 0);
            if (f == 2) { excl += atomicAdd(&d_scan_inc[p], 0); break; }
            excl += atomicAdd(&d_scan_agg[p], 0);
            p--;
        }
        d_scan_inc[bid] = excl + block_tot;
        __threadfence();
        atomicExch(&d_scan_flag[bid], 2);
        excl_sh = excl;
    }
    __syncthreads();
    const int add = excl_sh + thr_excl;

    if (base + 15 < n) {
        #pragma unroll
        for (int j = 0; j < 4; j++) {
            int4 qv; qv.x = v[4*j] + add; qv.y = v[4*j+1] + add; qv.z = v[4*j+2] + add; qv.w = v[4*j+3] + add;
            *(int4*)(d_cnt + base + 4 * j) = qv;
        }
    } else {
        #pragma unroll
        for (int j = 0; j < 16; j++) if (base + j < n) d_cnt[base + j] = v[j] + add;
    }
}

__global__ void scatter_kernel(const int* __restrict__ eindex, int E) {
    int i = blockIdx.x * blockDim.x + threadIdx.x;
    if (i < E) {
        int tg = eindex[E + i];
        int pos = atomicAdd(&d_cnt[tg], 1);
        d_sorted[pos] = i;
    }
}

__global__ void finalize_kernel(const float* __restrict__ x, float* __restrict__ out, int n) {
    int i = blockIdx.x * blockDim.x + threadIdx.x;
    if (i < n) {
        unsigned u = ((const unsigned*)out)[i];
        unsigned bits = (u & 0x80000000u) ? (u ^ 0x80000000u) : ~u;
        float v = __uint_as_float(bits);
        if (isinf(v)) v = 0.0f;
        out[i] = v + x[i];
    }
}

// ======================= persistent edge kernel =======================
__global__ void __launch_bounds__(NTHR, 2)
edge_kernel(const float* __restrict__ x,
            const float* __restrict__ eweight,
            const int* __restrict__ eindex,
            const float* __restrict__ w1,
            const float* __restrict__ w2,
            const float* __restrict__ w3,
            const float* __restrict__ g1, const float* __restrict__ b1,
            const float* __restrict__ g2, const float* __restrict__ b2,
            const float* __restrict__ g3, const float* __restrict__ b3,
            float* __restrict__ out, int E, int ntiles)
{
    extern __shared__ float sm[];
    uint2* w1p = (uint2*)(sm + OFF_W1P);
    uint2* w2p = (uint2*)(sm + OFF_W2P);
    uint2* w3p = (uint2*)(sm + OFF_W3P);
    uint2* AB  = (uint2*)(sm + OFF_AB);
    float* MS  = sm + OFF_AB;
    float* g1s = sm + OFF_G1;
    float* b1s = sm + OFF_B1;
    float* g2s = sm + OFF_G2;
    float* b2s = sm + OFF_B2;
    float* g3s = sm + OFF_G3;
    float* b3s = sm + OFF_B3;
    int*   tgb[2] = { (int*)(sm + OFF_TG0), (int*)(sm + OFF_TG1) };
    int*   srb[2] = { (int*)(sm + OFF_SR0), (int*)(sm + OFF_SR1) };
    float* ewb[2] = { sm + OFF_EW0, sm + OFF_EW1 };

    const int t    = threadIdx.x;
    const int lane = t & 31;
    const int wid  = t >> 5;
    const int stride = gridDim.x;

    // ---- stage packed weights ONCE ----
    for (int i = t; i < 1024; i += NTHR) {            // w1: 16 kt x 64 c
        int kt = i >> 6, c = i & 63;
        float4 va = *(const float4*)(w1 + c * TWO_H + kt * 8);
        float4 vb = *(const float4*)(w1 + c * TWO_H + kt * 8 + 4);
        w1p[(kt*4 + 0) * WPS + c] = make_uint2(f2tf32(va.x), f2tf32(vb.x));
        w1p[(kt*4 + 1) * WPS + c] = make_uint2(f2tf32(va.y), f2tf32(vb.y));
        w1p[(kt*4 + 2) * WPS + c] = make_uint2(f2tf32(va.z), f2tf32(vb.z));
        w1p[(kt*4 + 3) * WPS + c] = make_uint2(f2tf32(va.w), f2tf32(vb.w));
    }
    for (int i = t; i < 512; i += NTHR) {             // w2, w3: 8 kt x 64 c
        int kt = i >> 6, c = i & 63;
        float4 va2 = *(const float4*)(w2 + c * HID + kt * 8);
        float4 vb2 = *(const float4*)(w2 + c * HID + kt * 8 + 4);
        float4 va3 = *(const float4*)(w3 + c * HID + kt * 8);
        float4 vb3 = *(const float4*)(w3 + c * HID + kt * 8 + 4);
        w2p[(kt*4 + 0) * WPS + c] = make_uint2(f2tf32(va2.x), f2tf32(vb2.x));
        w2p[(kt*4 + 1) * WPS + c] = make_uint2(f2tf32(va2.y), f2tf32(vb2.y));
        w2p[(kt*4 + 2) * WPS + c] = make_uint2(f2tf32(va2.z), f2tf32(vb2.z));
        w2p[(kt*4 + 3) * WPS + c] = make_uint2(f2tf32(va2.w), f2tf32(vb2.w));
        w3p[(kt*4 + 0) * WPS + c] = make_uint2(f2tf32(va3.x), f2tf32(vb3.x));
        w3p[(kt*4 + 1) * WPS + c] = make_uint2(f2tf32(va3.y), f2tf32(vb3.y));
        w3p[(kt*4 + 2) * WPS + c] = make_uint2(f2tf32(va3.z), f2tf32(vb3.z));
        w3p[(kt*4 + 3) * WPS + c] = make_uint2(f2tf32(va3.w), f2tf32(vb3.w));
    }
    if (t < 128) { g1s[t] = g1[t]; b1s[t] = b1[t]; }
    else if (t < 192) {
        int u = t - 128;
        g2s[u] = g2[u]; b2s[u] = b2[u]; g3s[u] = g3[u]; b3s[u] = b3[u];
    }

    // ---- meta prefetch machinery ----
    int   p_tgt = -1, p_src = 0;
    float p_ew  = 0.f;
    #define LOAD_META(TL)                                            \
        do {                                                         \
            p_tgt = -1; p_src = 0; p_ew = 0.f;                       \
            if (t < TILE && (TL) < ntiles) {                         \
                int ge = (TL) * TILE + t;                            \
                if (ge < E) {                                        \
                    int eid = d_sorted[ge];                          \
                    p_tgt = eindex[E + eid];                         \
                    p_src = eindex[eid];                             \
                    p_ew  = eweight[eid];                            \
                }                                                    \
            }                                                        \
        } while (0)

    const int tile0 = blockIdx.x;
    LOAD_META(tile0);
    if (t < TILE) { tgb[0][t] = p_tgt; srb[0][t] = p_src; ewb[0][t] = p_ew; }
    LOAD_META(tile0 + stride);

    const int grp  = lane >> 2;
    const int q    = lane & 3;
    const int r_lo = wid * 16 + grp;
    const int r_hi = r_lo + 8;
    const int rp   = wid * 8 + grp;

    int par = 0;
    for (int tile = tile0; tile < ntiles; tile += stride, par ^= 1) {
        __syncthreads();   // buf[par] visible; prev epilogue & staging done

        // write next tile's meta (buf[par^1] is free), then prefetch tile+2
        if (t < TILE) { tgb[par^1][t] = p_tgt; srb[par^1][t] = p_src; ewb[par^1][t] = p_ew; }
        LOAD_META(tile + 2 * stride);

        const int*   tgs = tgb[par];
        const int*   srs = srb[par];
        const float* ews = ewb[par];

        // ---- gather m-fragments into registers ----
        float mlo[32], mhi[32];
        {
            int tg = tgs[r_lo];
            if (tg >= 0) {
                const float* xi = x + (size_t)tg * HID;
                const float* xj = x + (size_t)srs[r_lo] * HID;
                float w = ews[r_lo];
                #pragma unroll
                for (int tt = 0; tt < 16; tt++) {
                    int c = q + 4 * tt;
                    float vi = __ldg(xi + c);
                    float vj = __ldg(xj + c);
                    mlo[tt]      = vi;
                    mlo[16 + tt] = w * (vj - vi);
                }
            } else {
                #pragma unroll
                for (int tt = 0; tt < 32; tt++) mlo[tt] = 0.0f;
            }
        }
        {
            int tg = tgs[r_hi];
            if (tg >= 0) {
                const float* xi = x + (size_t)tg * HID;
                const float* xj = x + (size_t)srs[r_hi] * HID;
                float w = ews[r_hi];
                #pragma unroll
                for (int tt = 0; tt < 16; tt++) {
                    int c = q + 4 * tt;
                    float vi = __ldg(xi + c);
                    float vj = __ldg(xj + c);
                    mhi[tt]      = vi;
                    mhi[16 + tt] = w * (vj - vi);
                }
            } else {
                #pragma unroll
                for (int tt = 0; tt < 32; tt++) mhi[tt] = 0.0f;
            }
        }

        // ---- LN1 (width 128) in registers ----
        {
            float s_lo = 0.f, q_lo = 0.f, s_hi = 0.f, q_hi = 0.f;
            #pragma unroll
            for (int tt = 0; tt < 32; tt++) {
                s_lo += mlo[tt]; q_lo += mlo[tt] * mlo[tt];
                s_hi += mhi[tt]; q_hi += mhi[tt] * mhi[tt];
            }
            #pragma unroll
            for (int o = 1; o <= 2; o <<= 1) {
                s_lo += __shfl_xor_sync(0xffffffffu, s_lo, o);
                q_lo += __shfl_xor_sync(0xffffffffu, q_lo, o);
                s_hi += __shfl_xor_sync(0xffffffffu, s_hi, o);
                q_hi += __shfl_xor_sync(0xffffffffu, q_hi, o);
            }
            float mu_lo = s_lo * (1.0f / 128.0f);
            float mu_hi = s_hi * (1.0f / 128.0f);
            float r_l   = rsqrtf(fmaxf(q_lo * (1.0f / 128.0f) - mu_lo * mu_lo, 0.0f) + EPSF);
            float r_h   = rsqrtf(fmaxf(q_hi * (1.0f / 128.0f) - mu_hi * mu_hi, 0.0f) + EPSF);
            #pragma unroll
            for (int tt = 0; tt < 32; tt++) {
                int c = q + 4 * tt;
                float g = g1s[c], b = b1s[c];
                float h0 = (mlo[tt] - mu_lo) * r_l * g + b;
                float h1 = (mhi[tt] - mu_hi) * r_h * g + b;
                h0 = h0 > 0.f ? h0 : SLOPEF * h0;
                h1 = h1 > 0.f ? h1 : SLOPEF * h1;
                mlo[tt] = __uint_as_float(f2tf32(h0));
                mhi[tt] = __uint_as_float(f2tf32(h1));
            }
        }

        float acc[8][4];

        // ===== GEMM1 (A regs, B = persistent w1p) =====
        #pragma unroll
        for (int nt = 0; nt < 8; nt++)
            #pragma unroll
            for (int j = 0; j < 4; j++) acc[nt][j] = 0.0f;
        #pragma unroll
        for (int kt = 0; kt < 16; kt++) {
            uint32_t a0 = __float_as_uint(mlo[2 * kt]);
            uint32_t a1 = __float_as_uint(mhi[2 * kt]);
            uint32_t a2 = __float_as_uint(mlo[2 * kt + 1]);
            uint32_t a3 = __float_as_uint(mhi[2 * kt + 1]);
            const uint2* wrow = w1p + (kt * 4 + q) * WPS + grp;
            #pragma unroll
            for (int nt = 0; nt < 8; nt++) {
                uint2 bb = wrow[nt * 8];
                mma_tf32(acc[nt], a0, a1, a2, a3, bb.x, bb.y);
            }
        }

        // ---- LN2 in registers -> AB (warp-private rows; prev MS reads done at loop-top) ----
        {
            float s_lo = 0.f, q_lo = 0.f, s_hi = 0.f, q_hi = 0.f;
            #pragma unroll
            for (int nt = 0; nt < 8; nt++) {
                s_lo += acc[nt][0] + acc[nt][1];
                q_lo += acc[nt][0]*acc[nt][0] + acc[nt][1]*acc[nt][1];
                s_hi += acc[nt][2] + acc[nt][3];
                q_hi += acc[nt][2]*acc[nt][2] + acc[nt][3]*acc[nt][3];
            }
            #pragma unroll
            for (int o = 1; o <= 2; o <<= 1) {
                s_lo += __shfl_xor_sync(0xffffffffu, s_lo, o);
                q_lo += __shfl_xor_sync(0xffffffffu, q_lo, o);
                s_hi += __shfl_xor_sync(0xffffffffu, s_hi, o);
                q_hi += __shfl_xor_sync(0xffffffffu, q_hi, o);
            }
            float mu_lo = s_lo * (1.0f/64.0f);
            float mu_hi = s_hi * (1.0f/64.0f);
            float r_l   = rsqrtf(fmaxf(q_lo * (1.0f/64.0f) - mu_lo*mu_lo, 0.0f) + EPSF);
            float r_h   = rsqrtf(fmaxf(q_hi * (1.0f/64.0f) - mu_hi*mu_hi, 0.0f) + EPSF);

            #pragma unroll
            for (int nt = 0; nt < 8; nt++) {
                int c0 = nt * 8 + 2 * q;
                float2 g = *(float2*)(g2s + c0);
                float2 b = *(float2*)(b2s + c0);
                float h0 = (acc[nt][0] - mu_lo) * r_l * g.x + b.x;
                float h1 = (acc[nt][1] - mu_lo) * r_l * g.y + b.y;
                float h2 = (acc[nt][2] - mu_hi) * r_h * g.x + b.x;
                float h3 = (acc[nt][3] - mu_hi) * r_h * g.y + b.y;
                h0 = h0 > 0.f ? h0 : SLOPEF * h0;
                h1 = h1 > 0.f ? h1 : SLOPEF * h1;
                h2 = h2 > 0.f ? h2 : SLOPEF * h2;
                h3 = h3 > 0.f ? h3 : SLOPEF * h3;
                uint4 pk = make_uint4(f2tf32(h0), f2tf32(h2), f2tf32(h1), f2tf32(h3));
                *(uint4*)(AB + rp * APS + c0) = pk;
            }
        }
        __syncwarp();

        // ===== GEMM2 =====
        #pragma unroll
        for (int nt = 0; nt < 8; nt++)
            #pragma unroll
            for (int j = 0; j < 4; j++) acc[nt][j] = 0.0f;
        {
            const uint2* Ab = AB + rp * APS;
            #pragma unroll
            for (int kt = 0; kt < 8; kt++) {
                uint2 lo = Ab[kt * 8 + q];
                uint2 hi = Ab[kt * 8 + 4 + q];
                const uint2* wrow = w2p + (kt * 4 + q) * WPS + grp;
                #pragma unroll
                for (int nt = 0; nt < 8; nt++) {
                    uint2 bb = wrow[nt * 8];
                    mma_tf32(acc[nt], lo.x, lo.y, hi.x, hi.y, bb.x, bb.y);
                }
            }
        }
        __syncwarp();   // all lanes done reading AB before LN3 overwrites it

        // ---- LN3 in registers -> AB (overlay, warp-private) ----
        {
            float s_lo = 0.f, q_lo = 0.f, s_hi = 0.f, q_hi = 0.f;
            #pragma unroll
            for (int nt = 0; nt < 8; nt++) {
                s_lo += acc[nt][0] + acc[nt][1];
                q_lo += acc[nt][0]*acc[nt][0] + acc[nt][1]*acc[nt][1];
                s_hi += acc[nt][2] + acc[nt][3];
                q_hi += acc[nt][2]*acc[nt][2] + acc[nt][3]*acc[nt][3];
            }
            #pragma unroll
            for (int o = 1; o <= 2; o <<= 1) {
                s_lo += __shfl_xor_sync(0xffffffffu, s_lo, o);
                q_lo += __shfl_xor_sync(0xffffffffu, q_lo, o);
                s_hi += __shfl_xor_sync(0xffffffffu, s_hi, o);
                q_hi += __shfl_xor_sync(0xffffffffu, q_hi, o);
            }
            float mu_lo = s_lo * (1.0f/64.0f);
            float mu_hi = s_hi * (1.0f/64.0f);
            float r_l   = rsqrtf(fmaxf(q_lo * (1.0f/64.0f) - mu_lo*mu_lo, 0.0f) + EPSF);
            float r_h   = rsqrtf(fmaxf(q_hi * (1.0f/64.0f) - mu_hi*mu_hi, 0.0f) + EPSF);

            #pragma unroll
            for (int nt = 0; nt < 8; nt++) {
                int c0 = nt * 8 + 2 * q;
                float2 g = *(float2*)(g3s + c0);
                float2 b = *(float2*)(b3s + c0);
                float h0 = (acc[nt][0] - mu_lo) * r_l * g.x + b.x;
                float h1 = (acc[nt][1] - mu_lo) * r_l * g.y + b.y;
                float h2 = (acc[nt][2] - mu_hi) * r_h * g.x + b.x;
                float h3 = (acc[nt][3] - mu_hi) * r_h * g.y + b.y;
                h0 = h0 > 0.f ? h0 : SLOPEF * h0;
                h1 = h1 > 0.f ? h1 : SLOPEF * h1;
                h2 = h2 > 0.f ? h2 : SLOPEF * h2;
                h3 = h3 > 0.f ? h3 : SLOPEF * h3;
                uint4 pk = make_uint4(f2tf32(h0), f2tf32(h2), f2tf32(h1), f2tf32(h3));
                *(uint4*)(AB + rp * APS + c0) = pk;
            }
        }
        __syncwarp();

        // ===== GEMM3, stage messages into MS (overlays AB, warp-private) =====
        #pragma unroll
        for (int nt = 0; nt < 8; nt++)
            #pragma unroll
            for (int j = 0; j < 4; j++) acc[nt][j] = 0.0f;
        {
            const uint2* Ab = AB + rp * APS;
            #pragma unroll
            for (int kt = 0; kt < 8; kt++) {
                uint2 lo = Ab[kt * 8 + q];
                uint2 hi = Ab[kt * 8 + 4 + q];
                const uint2* wrow = w3p + (kt * 4 + q) * WPS + grp;
                #pragma unroll
                for (int nt = 0; nt < 8; nt++) {
                    uint2 bb = wrow[nt * 8];
                    mma_tf32(acc[nt], lo.x, lo.y, hi.x, hi.y, bb.x, bb.y);
                }
            }
        }
        __syncwarp();
        #pragma unroll
        for (int nt = 0; nt < 8; nt++) {
            int c0 = nt * 8 + 2 * q;
            float* o = MS + r_lo * MSS + c0;
            *(float2*)o             = make_float2(acc[nt][0], acc[nt][1]);
            *(float2*)(o + 8 * MSS) = make_float2(acc[nt][2], acc[nt][3]);
        }
        __syncthreads();

        // ---- run-aggregated segment-max epilogue ----
        {
            unsigned* outu = (unsigned*)out;
            const int c  = t & 63;
            const int gi = t >> 6;
            const int rs = gi * 32;
            float m = NEG_INF_F;
            int cur = tgs[rs];
            #pragma unroll 4
            for (int r = rs; r < rs + 32; r++) {
                int tg2 = tgs[r];
                if (tg2 != cur) {
                    if (cur >= 0) atomicMax(outu + (unsigned)cur * HID + c, fkey(m));
                    cur = tg2;
                    m = NEG_INF_F;
                }
                m = fmaxf(m, MS[r * MSS + c]);
            }
            if (cur >= 0) atomicMax(outu + (unsigned)cur * HID + c, fkey(m));
        }
    }
    #undef LOAD_META
}

extern "C" void kernel_launch(void* const* d_in, const int* in_sizes, int n_in,
                              void* d_out, int out_size) {
    const float* x  = (const float*)d_in[0];
    const float* ew = (const float*)d_in[1];
    const int*   ei = (const int*)d_in[2];
    const float* w1 = (const float*)d_in[3];
    const float* w2 = (const float*)d_in[4];
    const float* w3 = (const float*)d_in[5];
    const float* g1 = (const float*)d_in[6];
    const float* b1 = (const float*)d_in[7];
    const float* g2 = (const float*)d_in[8];
    const float* b2 = (const float*)d_in[9];
    const float* g3 = (const float*)d_in[10];
    const float* b3 = (const float*)d_in[11];
    float* out = (float*)d_out;

    const int E  = in_sizes[1];
    const int NH = out_size;
    const int N  = NH / HID;
    const int n  = N + 1;
    const int nchunk = (n + SCAN_CHUNK - 1) / SCAN_CHUNK;
    const int ntiles = (E + TILE - 1) / TILE;

    int nsm = 148;
    cudaDeviceGetAttribute(&nsm, cudaDevAttrMultiProcessorCount, 0);
    int nblocks = 2 * nsm;
    if (nblocks > ntiles) nblocks = ntiles;

    cudaFuncSetAttribute(edge_kernel, cudaFuncAttributeMaxDynamicSharedMemorySize, SMEM_BYTES);

    int zi_n = (n > NH / 4) ? n : NH / 4;
    zero_init_kernel<<<(zi_n + 255) / 256, 256>>>(n, (uint4*)out, NH / 4);
    hist_kernel<<<(E + 255) / 256, 256>>>(ei, E);
    scan_lb_kernel<<<nchunk, 256>>>(n);
    scatter_kernel<<<(E + 255) / 256, 256>>>(ei, E);
    edge_kernel<<<nblocks, NTHR, SMEM_BYTES>>>(
        x, ew, ei, w1, w2, w3, g1, b1, g2, b2, g3, b3, out, E, ntiles);
    finalize_kernel<<<(NH + 255) / 256, 256>>>(x, out, NH);
}

// round 10
// speedup vs baseline: 1.3368x; 1.0077x over previous
#include <cuda_runtime.h>
#include <math.h>
#include <stdint.h>

#define HID     64
#define TWO_H   128
#define TILE    128
#define NTHR    256
#define EPSF    1e-5f
#define SLOPEF  0.2f

#define WPS     68
#define APS     68
#define MSS     68

// shared memory layout (float offsets)
#define OFF_W1P 0
#define OFF_W2P 8704
#define OFF_W3P 13056
#define OFF_AB  17408
#define OFF_G1  26112
#define OFF_B1  26240
#define OFF_G2  26368
#define OFF_B2  26432
#define OFF_G3  26496
#define OFF_B3  26560
#define OFF_TG0 26624
#define OFF_TG1 26752
#define OFF_SR0 26880
#define OFF_SR1 27008
#define OFF_EW0 27136
#define OFF_EW1 27264
#define SMEM_FLOATS 27392
#define SMEM_BYTES  (SMEM_FLOATS * 4)   // 109,568 B -> 2 blocks/SM

// -------- sort scratch --------
#define MAXN 262145
#define MAXE 1048576
#define SCAN_CHUNK 4096
#define MAXCHUNK 128
__device__ int d_cnt[MAXN + 1];
__device__ int d_sorted[MAXE];
__device__ int d_scan_flag[MAXCHUNK];
__device__ int d_scan_agg[MAXCHUNK];
__device__ int d_scan_inc[MAXCHUNK];
__device__ int d_scan_done;

__device__ __forceinline__ unsigned fkey(float v) {
    unsigned u = __float_as_uint(v);
    return u ^ (unsigned)(((int)u >> 31) | 0x80000000);
}
#define KEY_NEG_INF 0x007FFFFFu
#define NEG_INF_F   __int_as_float(0xFF800000)

__device__ __forceinline__ uint32_t f2tf32(float f) {
    uint32_t r;
    asm("cvt.rna.tf32.f32 %0, %1;" : "=r"(r) : "f"(f));
    return r;
}

__device__ __forceinline__ void mma_tf32(float acc[4],
                                         uint32_t a0, uint32_t a1, uint32_t a2, uint32_t a3,
                                         uint32_t b0, uint32_t b1) {
    asm volatile(
        "mma.sync.aligned.m16n8k8.row.col.f32.tf32.tf32.f32 "
        "{%0,%1,%2,%3}, {%4,%5,%6,%7}, {%8,%9}, {%0,%1,%2,%3};"
        : "+f"(acc[0]), "+f"(acc[1]), "+f"(acc[2]), "+f"(acc[3])
        : "r"(a0), "r"(a1), "r"(a2), "r"(a3), "r"(b0), "r"(b1));
}

// ============ launch 1: zero scratch + init output keys ============
__global__ void zero_init_kernel(int n, uint4* __restrict__ out, int n4) {
    int i = blockIdx.x * blockDim.x + threadIdx.x;
    if (i < n) d_cnt[i] = 0;
    if (i < MAXCHUNK) d_scan_flag[i] = 0;
    if (i == MAXCHUNK) d_scan_done = 0;
    if (i < n4) out[i] = make_uint4(KEY_NEG_INF, KEY_NEG_INF, KEY_NEG_INF, KEY_NEG_INF);
}

// ============ launch 2: histogram ============
__global__ void hist_kernel(const int* __restrict__ eindex, int E) {
    int i = blockIdx.x * blockDim.x + threadIdx.x;
    if (i < E) atomicAdd(&d_cnt[eindex[E + i] + 1], 1);
}

// ============ launch 3: fused scan (lookback) + grid barrier + scatter ============
__global__ void __launch_bounds__(256)
scan_scatter_kernel(const int* __restrict__ eindex, int E, int n, int nchunk) {
    const int t = threadIdx.x, lane = t & 31, w = t >> 5;
    const int bid = blockIdx.x;

    if (bid < nchunk) {
        __shared__ int warp_tot[8];
        __shared__ int excl_sh;
        const int base = bid * SCAN_CHUNK + t * 16;

        int v[16];
        if (base + 15 < n) {
            #pragma unroll
            for (int j = 0; j < 4; j++) {
                int4 qv = *(const int4*)(d_cnt + base + 4 * j);
                v[4*j] = qv.x; v[4*j+1] = qv.y; v[4*j+2] = qv.z; v[4*j+3] = qv.w;
            }
        } else {
            #pragma unroll
            for (int j = 0; j < 16; j++) v[j] = (base + j < n) ? d_cnt[base + j] : 0;
        }
        #pragma unroll
        for (int j = 1; j < 16; j++) v[j] += v[j - 1];

        int s = v[15];
        #pragma unroll
        for (int o = 1; o < 32; o <<= 1) {
            int u = __shfl_up_sync(0xffffffffu, s, o);
            if (lane >= o) s += u;
        }
        if (lane == 31) warp_tot[w] = s;
        __syncthreads();
        if (w == 0) {
            int ws = (lane < 8) ? warp_tot[lane] : 0;
            #pragma unroll
            for (int o = 1; o < 8; o <<= 1) {
                int u = __shfl_up_sync(0xffffffffu, ws, o);
                if (lane >= o) ws += u;
            }
            if (lane < 8) warp_tot[lane] = ws;
        }
        __syncthreads();
        const int block_tot = warp_tot[7];
        const int thr_excl  = (s - v[15]) + (w > 0 ? warp_tot[w - 1] : 0);

        if (t == 0) {
            d_scan_agg[bid] = block_tot;
            __threadfence();
            atomicExch(&d_scan_flag[bid], 1);
            int excl = 0;
            for (int p = bid - 1; p >= 0; ) {
                int f;
                do { f = atomicAdd(&d_scan_flag[p], 0); } while (f == 0);
                if (f == 2) { excl += atomicAdd(&d_scan_inc[p], 0); break; }
                excl += atomicAdd(&d_scan_agg[p], 0);
                p--;
            }
            d_scan_inc[bid] = excl + block_tot;
            __threadfence();
            atomicExch(&d_scan_flag[bid], 2);
            excl_sh = excl;
        }
        __syncthreads();
        const int add = excl_sh + thr_excl;

        if (base + 15 < n) {
            #pragma unroll
            for (int j = 0; j < 4; j++) {
                int4 qv; qv.x = v[4*j] + add; qv.y = v[4*j+1] + add; qv.z = v[4*j+2] + add; qv.w = v[4*j+3] + add;
                *(int4*)(d_cnt + base + 4 * j) = qv;
            }
        } else {
            #pragma unroll
            for (int j = 0; j < 16; j++) if (base + j < n) d_cnt[base + j] = v[j] + add;
        }
        __syncthreads();
        if (t == 0) { __threadfence(); atomicAdd(&d_scan_done, 1); }
    }

    // grid barrier: wait for all scan chunks (grid fully resident at 4 blocks/SM)
    if (t == 0) {
        while (atomicAdd(&d_scan_done, 0) < nchunk) { }
    }
    __syncthreads();
    __threadfence();

    // scatter, strided over edges
    for (int i = bid * 256 + t; i < E; i += gridDim.x * 256) {
        int tg = eindex[E + i];
        int pos = atomicAdd(&d_cnt[tg], 1);
        d_sorted[pos] = i;
    }
}

// ============ launch 5: finalize ============
__global__ void finalize_kernel(const float* __restrict__ x, float* __restrict__ out, int n) {
    int i = blockIdx.x * blockDim.x + threadIdx.x;
    if (i < n) {
        unsigned u = ((const unsigned*)out)[i];
        unsigned bits = (u & 0x80000000u) ? (u ^ 0x80000000u) : ~u;
        float v = __uint_as_float(bits);
        if (isinf(v)) v = 0.0f;
        out[i] = v + x[i];
    }
}

// ============ launch 4: persistent edge kernel ============
__global__ void __launch_bounds__(NTHR, 2)
edge_kernel(const float* __restrict__ x,
            const float* __restrict__ eweight,
            const int* __restrict__ eindex,
            const float* __restrict__ w1,
            const float* __restrict__ w2,
            const float* __restrict__ w3,
            const float* __restrict__ g1, const float* __restrict__ b1,
            const float* __restrict__ g2, const float* __restrict__ b2,
            const float* __restrict__ g3, const float* __restrict__ b3,
            float* __restrict__ out, int E, int ntiles)
{
    extern __shared__ float sm[];
    uint2* w1p = (uint2*)(sm + OFF_W1P);
    uint2* w2p = (uint2*)(sm + OFF_W2P);
    uint2* w3p = (uint2*)(sm + OFF_W3P);
    uint2* AB  = (uint2*)(sm + OFF_AB);
    float* MS  = sm + OFF_AB;
    float* g1s = sm + OFF_G1;
    float* b1s = sm + OFF_B1;
    float* g2s = sm + OFF_G2;
    float* b2s = sm + OFF_B2;
    float* g3s = sm + OFF_G3;
    float* b3s = sm + OFF_B3;
    int*   tgb[2] = { (int*)(sm + OFF_TG0), (int*)(sm + OFF_TG1) };
    int*   srb[2] = { (int*)(sm + OFF_SR0), (int*)(sm + OFF_SR1) };
    float* ewb[2] = { sm + OFF_EW0, sm + OFF_EW1 };

    const int t    = threadIdx.x;
    const int lane = t & 31;
    const int wid  = t >> 5;
    const int stride = gridDim.x;

    // ---- stage packed weights ONCE ----
    for (int i = t; i < 1024; i += NTHR) {
        int kt = i >> 6, c = i & 63;
        float4 va = *(const float4*)(w1 + c * TWO_H + kt * 8);
        float4 vb = *(const float4*)(w1 + c * TWO_H + kt * 8 + 4);
        w1p[(kt*4 + 0) * WPS + c] = make_uint2(f2tf32(va.x), f2tf32(vb.x));
        w1p[(kt*4 + 1) * WPS + c] = make_uint2(f2tf32(va.y), f2tf32(vb.y));
        w1p[(kt*4 + 2) * WPS + c] = make_uint2(f2tf32(va.z), f2tf32(vb.z));
        w1p[(kt*4 + 3) * WPS + c] = make_uint2(f2tf32(va.w), f2tf32(vb.w));
    }
    for (int i = t; i < 512; i += NTHR) {
        int kt = i >> 6, c = i & 63;
        float4 va2 = *(const float4*)(w2 + c * HID + kt * 8);
        float4 vb2 = *(const float4*)(w2 + c * HID + kt * 8 + 4);
        float4 va3 = *(const float4*)(w3 + c * HID + kt * 8);
        float4 vb3 = *(const float4*)(w3 + c * HID + kt * 8 + 4);
        w2p[(kt*4 + 0) * WPS + c] = make_uint2(f2tf32(va2.x), f2tf32(vb2.x));
        w2p[(kt*4 + 1) * WPS + c] = make_uint2(f2tf32(va2.y), f2tf32(vb2.y));
        w2p[(kt*4 + 2) * WPS + c] = make_uint2(f2tf32(va2.z), f2tf32(vb2.z));
        w2p[(kt*4 + 3) * WPS + c] = make_uint2(f2tf32(va2.w), f2tf32(vb2.w));
        w3p[(kt*4 + 0) * WPS + c] = make_uint2(f2tf32(va3.x), f2tf32(vb3.x));
        w3p[(kt*4 + 1) * WPS + c] = make_uint2(f2tf32(va3.y), f2tf32(vb3.y));
        w3p[(kt*4 + 2) * WPS + c] = make_uint2(f2tf32(va3.z), f2tf32(vb3.z));
        w3p[(kt*4 + 3) * WPS + c] = make_uint2(f2tf32(va3.w), f2tf32(vb3.w));
    }
    if (t < 128) { g1s[t] = g1[t]; b1s[t] = b1[t]; }
    else if (t < 192) {
        int u = t - 128;
        g2s[u] = g2[u]; b2s[u] = b2[u]; g3s[u] = g3[u]; b3s[u] = b3[u];
    }

    int   p_tgt = -1, p_src = 0;
    float p_ew  = 0.f;
    #define LOAD_META(TL)                                            \
        do {                                                         \
            p_tgt = -1; p_src = 0; p_ew = 0.f;                       \
            if (t < TILE && (TL) < ntiles) {                         \
                int ge = (TL) * TILE + t;                            \
                if (ge < E) {                                        \
                    int eid = d_sorted[ge];                          \
                    p_tgt = eindex[E + eid];                         \
                    p_src = eindex[eid];                             \
                    p_ew  = eweight[eid];                            \
                }                                                    \
            }                                                        \
        } while (0)

    const int tile0 = blockIdx.x;
    LOAD_META(tile0);
    if (t < TILE) { tgb[0][t] = p_tgt; srb[0][t] = p_src; ewb[0][t] = p_ew; }
    LOAD_META(tile0 + stride);

    const int grp  = lane >> 2;
    const int q    = lane & 3;
    const int r_lo = wid * 16 + grp;
    const int r_hi = r_lo + 8;
    const int rp   = wid * 8 + grp;

    int par = 0;
    for (int tile = tile0; tile < ntiles; tile += stride, par ^= 1) {
        __syncthreads();   // meta buf[par] visible; prev epilogue reads of tgb[par^1] done

        if (t < TILE) { tgb[par^1][t] = p_tgt; srb[par^1][t] = p_src; ewb[par^1][t] = p_ew; }
        LOAD_META(tile + 2 * stride);

        const int*   tgs = tgb[par];
        const int*   srs = srb[par];
        const float* ews = ewb[par];

        // ---- gather m-fragments into registers ----
        float mlo[32], mhi[32];
        {
            int tg = tgs[r_lo];
            if (tg >= 0) {
                const float* xi = x + (size_t)tg * HID;
                const float* xj = x + (size_t)srs[r_lo] * HID;
                float w = ews[r_lo];
                #pragma unroll
                for (int tt = 0; tt < 16; tt++) {
                    int c = q + 4 * tt;
                    float vi = __ldg(xi + c);
                    float vj = __ldg(xj + c);
                    mlo[tt]      = vi;
                    mlo[16 + tt] = w * (vj - vi);
                }
            } else {
                #pragma unroll
                for (int tt = 0; tt < 32; tt++) mlo[tt] = 0.0f;
            }
        }
        {
            int tg = tgs[r_hi];
            if (tg >= 0) {
                const float* xi = x + (size_t)tg * HID;
                const float* xj = x + (size_t)srs[r_hi] * HID;
                float w = ews[r_hi];
                #pragma unroll
                for (int tt = 0; tt < 16; tt++) {
                    int c = q + 4 * tt;
                    float vi = __ldg(xi + c);
                    float vj = __ldg(xj + c);
                    mhi[tt]      = vi;
                    mhi[16 + tt] = w * (vj - vi);
                }
            } else {
                #pragma unroll
                for (int tt = 0; tt < 32; tt++) mhi[tt] = 0.0f;
            }
        }

        // ---- LN1 in registers ----
        {
            float s_lo = 0.f, q_lo = 0.f, s_hi = 0.f, q_hi = 0.f;
            #pragma unroll
            for (int tt = 0; tt < 32; tt++) {
                s_lo += mlo[tt]; q_lo += mlo[tt] * mlo[tt];
                s_hi += mhi[tt]; q_hi += mhi[tt] * mhi[tt];
            }
            #pragma unroll
            for (int o = 1; o <= 2; o <<= 1) {
                s_lo += __shfl_xor_sync(0xffffffffu, s_lo, o);
                q_lo += __shfl_xor_sync(0xffffffffu, q_lo, o);
                s_hi += __shfl_xor_sync(0xffffffffu, s_hi, o);
                q_hi += __shfl_xor_sync(0xffffffffu, q_hi, o);
            }
            float mu_lo = s_lo * (1.0f / 128.0f);
            float mu_hi = s_hi * (1.0f / 128.0f);
            float r_l   = rsqrtf(fmaxf(q_lo * (1.0f / 128.0f) - mu_lo * mu_lo, 0.0f) + EPSF);
            float r_h   = rsqrtf(fmaxf(q_hi * (1.0f / 128.0f) - mu_hi * mu_hi, 0.0f) + EPSF);
            #pragma unroll
            for (int tt = 0; tt < 32; tt++) {
                int c = q + 4 * tt;
                float g = g1s[c], b = b1s[c];
                float h0 = (mlo[tt] - mu_lo) * r_l * g + b;
                float h1 = (mhi[tt] - mu_hi) * r_h * g + b;
                h0 = h0 > 0.f ? h0 : SLOPEF * h0;
                h1 = h1 > 0.f ? h1 : SLOPEF * h1;
                mlo[tt] = __uint_as_float(f2tf32(h0));
                mhi[tt] = __uint_as_float(f2tf32(h1));
            }
        }

        float acc[8][4];

        // ===== GEMM1 =====
        #pragma unroll
        for (int nt = 0; nt < 8; nt++)
            #pragma unroll
            for (int j = 0; j < 4; j++) acc[nt][j] = 0.0f;
        #pragma unroll
        for (int kt = 0; kt < 16; kt++) {
            uint32_t a0 = __float_as_uint(mlo[2 * kt]);
            uint32_t a1 = __float_as_uint(mhi[2 * kt]);
            uint32_t a2 = __float_as_uint(mlo[2 * kt + 1]);
            uint32_t a3 = __float_as_uint(mhi[2 * kt + 1]);
            const uint2* wrow = w1p + (kt * 4 + q) * WPS + grp;
            #pragma unroll
            for (int nt = 0; nt < 8; nt++) {
                uint2 bb = wrow[nt * 8];
                mma_tf32(acc[nt], a0, a1, a2, a3, bb.x, bb.y);
            }
        }

        // ---- LN2 -> AB (warp-private) ----
        {
            float s_lo = 0.f, q_lo = 0.f, s_hi = 0.f, q_hi = 0.f;
            #pragma unroll
            for (int nt = 0; nt < 8; nt++) {
                s_lo += acc[nt][0] + acc[nt][1];
                q_lo += acc[nt][0]*acc[nt][0] + acc[nt][1]*acc[nt][1];
                s_hi += acc[nt][2] + acc[nt][3];
                q_hi += acc[nt][2]*acc[nt][2] + acc[nt][3]*acc[nt][3];
            }
            #pragma unroll
            for (int o = 1; o <= 2; o <<= 1) {
                s_lo += __shfl_xor_sync(0xffffffffu, s_lo, o);
                q_lo += __shfl_xor_sync(0xffffffffu, q_lo, o);
                s_hi += __shfl_xor_sync(0xffffffffu, s_hi, o);
                q_hi += __shfl_xor_sync(0xffffffffu, q_hi, o);
            }
            float mu_lo = s_lo * (1.0f/64.0f);
            float mu_hi = s_hi * (1.0f/64.0f);
            float r_l   = rsqrtf(fmaxf(q_lo * (1.0f/64.0f) - mu_lo*mu_lo, 0.0f) + EPSF);
            float r_h   = rsqrtf(fmaxf(q_hi * (1.0f/64.0f) - mu_hi*mu_hi, 0.0f) + EPSF);

            #pragma unroll
            for (int nt = 0; nt < 8; nt++) {
                int c0 = nt * 8 + 2 * q;
                float2 g = *(float2*)(g2s + c0);
                float2 b = *(float2*)(b2s + c0);
                float h0 = (acc[nt][0] - mu_lo) * r_l * g.x + b.x;
                float h1 = (acc[nt][1] - mu_lo) * r_l * g.y + b.y;
                float h2 = (acc[nt][2] - mu_hi) * r_h * g.x + b.x;
                float h3 = (acc[nt][3] - mu_hi) * r_h * g.y + b.y;
                h0 = h0 > 0.f ? h0 : SLOPEF * h0;
                h1 = h1 > 0.f ? h1 : SLOPEF * h1;
                h2 = h2 > 0.f ? h2 : SLOPEF * h2;
                h3 = h3 > 0.f ? h3 : SLOPEF * h3;
                uint4 pk = make_uint4(f2tf32(h0), f2tf32(h2), f2tf32(h1), f2tf32(h3));
                *(uint4*)(AB + rp * APS + c0) = pk;
            }
        }
        __syncwarp();

        // ===== GEMM2 =====
        #pragma unroll
        for (int nt = 0; nt < 8; nt++)
            #pragma unroll
            for (int j = 0; j < 4; j++) acc[nt][j] = 0.0f;
        {
            const uint2* Ab = AB + rp * APS;
            #pragma unroll
            for (int kt = 0; kt < 8; kt++) {
                uint2 lo = Ab[kt * 8 + q];
                uint2 hi = Ab[kt * 8 + 4 + q];
                const uint2* wrow = w2p + (kt * 4 + q) * WPS + grp;
                #pragma unroll
                for (int nt = 0; nt < 8; nt++) {
                    uint2 bb = wrow[nt * 8];
                    mma_tf32(acc[nt], lo.x, lo.y, hi.x, hi.y, bb.x, bb.y);
                }
            }
        }
        __syncwarp();

        // ---- LN3 -> AB ----
        {
            float s_lo = 0.f, q_lo = 0.f, s_hi = 0.f, q_hi = 0.f;
            #pragma unroll
            for (int nt = 0; nt < 8; nt++) {
                s_lo += acc[nt][0] + acc[nt][1];
                q_lo += acc[nt][0]*acc[nt][0] + acc[nt][1]*acc[nt][1];
                s_hi += acc[nt][2] + acc[nt][3];
                q_hi += acc[nt][2]*acc[nt][2] + acc[nt][3]*acc[nt][3];
            }
            #pragma unroll
            for (int o = 1; o <= 2; o <<= 1) {
                s_lo += __shfl_xor_sync(0xffffffffu, s_lo, o);
                q_lo += __shfl_xor_sync(0xffffffffu, q_lo, o);
                s_hi += __shfl_xor_sync(0xffffffffu, s_hi, o);
                q_hi += __shfl_xor_sync(0xffffffffu, q_hi, o);
            }
            float mu_lo = s_lo * (1.0f/64.0f);
            float mu_hi = s_hi * (1.0f/64.0f);
            float r_l   = rsqrtf(fmaxf(q_lo * (1.0f/64.0f) - mu_lo*mu_lo, 0.0f) + EPSF);
            float r_h   = rsqrtf(fmaxf(q_hi * (1.0f/64.0f) - mu_hi*mu_hi, 0.0f) + EPSF);

            #pragma unroll
            for (int nt = 0; nt < 8; nt++) {
                int c0 = nt * 8 + 2 * q;
                float2 g = *(float2*)(g3s + c0);
                float2 b = *(float2*)(b3s + c0);
                float h0 = (acc[nt][0] - mu_lo) * r_l * g.x + b.x;
                float h1 = (acc[nt][1] - mu_lo) * r_l * g.y + b.y;
                float h2 = (acc[nt][2] - mu_hi) * r_h * g.x + b.x;
                float h3 = (acc[nt][3] - mu_hi) * r_h * g.y + b.y;
                h0 = h0 > 0.f ? h0 : SLOPEF * h0;
                h1 = h1 > 0.f ? h1 : SLOPEF * h1;
                h2 = h2 > 0.f ? h2 : SLOPEF * h2;
                h3 = h3 > 0.f ? h3 : SLOPEF * h3;
                uint4 pk = make_uint4(f2tf32(h0), f2tf32(h2), f2tf32(h1), f2tf32(h3));
                *(uint4*)(AB + rp * APS + c0) = pk;
            }
        }
        __syncwarp();

        // ===== GEMM3 =====
        #pragma unroll
        for (int nt = 0; nt < 8; nt++)
            #pragma unroll
            for (int j = 0; j < 4; j++) acc[nt][j] = 0.0f;
        {
            const uint2* Ab = AB + rp * APS;
            #pragma unroll
            for (int kt = 0; kt < 8; kt++) {
                uint2 lo = Ab[kt * 8 + q];
                uint2 hi = Ab[kt * 8 + 4 + q];
                const uint2* wrow = w3p + (kt * 4 + q) * WPS + grp;
                #pragma unroll
                for (int nt = 0; nt < 8; nt++) {
                    uint2 bb = wrow[nt * 8];
                    mma_tf32(acc[nt], lo.x, lo.y, hi.x, hi.y, bb.x, bb.y);
                }
            }
        }
        __syncwarp();

        // stage this warp's 16 rows into its private MS slab
        #pragma unroll
        for (int nt = 0; nt < 8; nt++) {
            int c0 = nt * 8 + 2 * q;
            float* o = MS + r_lo * MSS + c0;
            *(float2*)o             = make_float2(acc[nt][0], acc[nt][1]);
            *(float2*)(o + 8 * MSS) = make_float2(acc[nt][2], acc[nt][3]);
        }
        __syncwarp();

        // ---- warp-local run-aggregated segment-max epilogue ----
        {
            unsigned* outu = (unsigned*)out;
            const int rs = wid * 16;
            #pragma unroll
            for (int half = 0; half < 2; half++) {
                const int c = lane + 32 * half;
                float m = NEG_INF_F;
                int cur = tgs[rs];
                #pragma unroll 4
                for (int r = rs; r < rs + 16; r++) {
                    int tg2 = tgs[r];
                    if (tg2 != cur) {
                        if (cur >= 0) atomicMax(outu + (unsigned)cur * HID + c, fkey(m));
                        cur = tg2;
                        m = NEG_INF_F;
                    }
                    m = fmaxf(m, MS[r * MSS + c]);
                }
                if (cur >= 0) atomicMax(outu + (unsigned)cur * HID + c, fkey(m));
            }
        }
    }
    #undef LOAD_META
}

extern "C" void kernel_launch(void* const* d_in, const int* in_sizes, int n_in,
                              void* d_out, int out_size) {
    const float* x  = (const float*)d_in[0];
    const float* ew = (const float*)d_in[1];
    const int*   ei = (const int*)d_in[2];
    const float* w1 = (const float*)d_in[3];
    const float* w2 = (const float*)d_in[4];
    const float* w3 = (const float*)d_in[5];
    const float* g1 = (const float*)d_in[6];
    const float* b1 = (const float*)d_in[7];
    const float* g2 = (const float*)d_in[8];
    const float* b2 = (const float*)d_in[9];
    const float* g3 = (const float*)d_in[10];
    const float* b3 = (const float*)d_in[11];
    float* out = (float*)d_out;

    const int E  = in_sizes[1];
    const int NH = out_size;
    const int N  = NH / HID;
    const int n  = N + 1;
    const int nchunk = (n + SCAN_CHUNK - 1) / SCAN_CHUNK;
    const int ntiles = (E + TILE - 1) / TILE;

    int nsm = 148;
    cudaDeviceGetAttribute(&nsm, cudaDevAttrMultiProcessorCount, 0);
    int nblocks = 2 * nsm;
    if (nblocks > ntiles) nblocks = ntiles;
    int ssblocks = 4 * nsm;   // fully resident -> grid barrier is safe

    cudaFuncSetAttribute(edge_kernel, cudaFuncAttributeMaxDynamicSharedMemorySize, SMEM_BYTES);

    int zi_n = (n > NH / 4) ? n : NH / 4;
    zero_init_kernel<<<(zi_n + 255) / 256, 256>>>(n, (uint4*)out, NH / 4);       // #1
    hist_kernel<<<(E + 255) / 256, 256>>>(ei, E);                                 // #2
    scan_scatter_kernel<<<ssblocks, 256>>>(ei, E, n, nchunk);                     // #3
    edge_kernel<<<nblocks, NTHR, SMEM_BYTES>>>(                                   // #4 (profiled)
        x, ew, ei, w1, w2, w3, g1, b1, g2, b2, g3, b3, out, E, ntiles);
    finalize_kernel<<<(NH + 255) / 256, 256>>>(x, out, NH);                       // #5
}

// round 12
// speedup vs baseline: 1.3628x; 1.0194x over previous
#include <cuda_runtime.h>
#include <math.h>
#include <stdint.h>

#define HID     64
#define TWO_H   128
#define TILE    128
#define NTHR    256
#define EPSF    1e-5f
#define SLOPEF  0.2f

#define WPS     68     // packed weight row stride (uint2 units)
#define APS2    66     // packed activation row-pair stride (uint2 units)
#define MSS     66     // message staging row stride (floats); 16*MSS == 8*2*APS2 (warp-slab exact)

// shared memory layout (float offsets)
#define OFF_W1P 0        // 64 x 68 uint2 = 8704 floats
#define OFF_W2P 8704     // 32 x 68 uint2 = 4352 floats
#define OFF_W3P 13056
#define OFF_AB  17408    // AB: 64 x 66 uint2 = 8448 floats; MS overlays (warp-private slabs)
#define OFF_G1  26112
#define OFF_B1  26240
#define OFF_G2  26368
#define OFF_B2  26432
#define OFF_G3  26496
#define OFF_B3  26560
#define OFF_TG0 26624
#define OFF_TG1 26752
#define OFF_SR0 26880
#define OFF_SR1 27008
#define OFF_EW0 27136
#define OFF_EW1 27264
#define SMEM_FLOATS 27392
#define SMEM_BYTES  (SMEM_FLOATS * 4)   // 109,568 B -> 2 blocks/SM

// -------- sort scratch --------
#define MAXN 262145
#define MAXE 1048576
#define SCAN_CHUNK 4096
#define MAXCHUNK 128
__device__ int d_cnt[MAXN + 1];
__device__ int d_sorted[MAXE];
__device__ int d_scan_flag[MAXCHUNK];
__device__ int d_scan_agg[MAXCHUNK];
__device__ int d_scan_inc[MAXCHUNK];
__device__ int d_scan_done;

__device__ __forceinline__ unsigned fkey(float v) {
    unsigned u = __float_as_uint(v);
    return u ^ (unsigned)(((int)u >> 31) | 0x80000000);
}
#define KEY_NEG_INF 0x007FFFFFu
#define NEG_INF_F   __int_as_float(0xFF800000)

__device__ __forceinline__ uint32_t f2tf32(float f) {
    uint32_t r;
    asm("cvt.rna.tf32.f32 %0, %1;" : "=r"(r) : "f"(f));
    return r;
}

__device__ __forceinline__ void mma_tf32(float acc[4],
                                         uint32_t a0, uint32_t a1, uint32_t a2, uint32_t a3,
                                         uint32_t b0, uint32_t b1) {
    asm volatile(
        "mma.sync.aligned.m16n8k8.row.col.f32.tf32.tf32.f32 "
        "{%0,%1,%2,%3}, {%4,%5,%6,%7}, {%8,%9}, {%0,%1,%2,%3};"
        : "+f"(acc[0]), "+f"(acc[1]), "+f"(acc[2]), "+f"(acc[3])
        : "r"(a0), "r"(a1), "r"(a2), "r"(a3), "r"(b0), "r"(b1));
}

// logical k-column for fragment slot (kt, q) in a K=64 block (lane-contiguous permutation)
__device__ __forceinline__ int kcol64(int kt, int q) {
    return 16 * (kt >> 1) + 4 * q + 2 * (kt & 1);
}

// ============ launch 1: zero scratch + init output keys ============
__global__ void zero_init_kernel(int n, uint4* __restrict__ out, int n4) {
    int i = blockIdx.x * blockDim.x + threadIdx.x;
    if (i < n) d_cnt[i] = 0;
    if (i < MAXCHUNK) d_scan_flag[i] = 0;
    if (i == MAXCHUNK) d_scan_done = 0;
    if (i < n4) out[i] = make_uint4(KEY_NEG_INF, KEY_NEG_INF, KEY_NEG_INF, KEY_NEG_INF);
}

// ============ launch 2: histogram ============
__global__ void hist_kernel(const int* __restrict__ eindex, int E) {
    int i = blockIdx.x * blockDim.x + threadIdx.x;
    if (i < E) atomicAdd(&d_cnt[eindex[E + i] + 1], 1);
}

// ============ launch 3: fused scan + grid barrier + scatter ============
__global__ void __launch_bounds__(256)
scan_scatter_kernel(const int* __restrict__ eindex, int E, int n, int nchunk) {
    const int t = threadIdx.x, lane = t & 31, w = t >> 5;
    const int bid = blockIdx.x;

    if (bid < nchunk) {
        __shared__ int warp_tot[8];
        __shared__ int excl_sh;
        const int base = bid * SCAN_CHUNK + t * 16;

        int v[16];
        if (base + 15 < n) {
            #pragma unroll
            for (int j = 0; j < 4; j++) {
                int4 qv = *(const int4*)(d_cnt + base + 4 * j);
                v[4*j] = qv.x; v[4*j+1] = qv.y; v[4*j+2] = qv.z; v[4*j+3] = qv.w;
            }
        } else {
            #pragma unroll
            for (int j = 0; j < 16; j++) v[j] = (base + j < n) ? d_cnt[base + j] : 0;
        }
        #pragma unroll
        for (int j = 1; j < 16; j++) v[j] += v[j - 1];

        int s = v[15];
        #pragma unroll
        for (int o = 1; o < 32; o <<= 1) {
            int u = __shfl_up_sync(0xffffffffu, s, o);
            if (lane >= o) s += u;
        }
        if (lane == 31) warp_tot[w] = s;
        __syncthreads();
        if (w == 0) {
            int ws = (lane < 8) ? warp_tot[lane] : 0;
            #pragma unroll
            for (int o = 1; o < 8; o <<= 1) {
                int u = __shfl_up_sync(0xffffffffu, ws, o);
                if (lane >= o) ws += u;
            }
            if (lane < 8) warp_tot[lane] = ws;
        }
        __syncthreads();
        const int block_tot = warp_tot[7];
        const int thr_excl  = (s - v[15]) + (w > 0 ? warp_tot[w - 1] : 0);

        if (t == 0) {
            d_scan_agg[bid] = block_tot;
            __threadfence();
            atomicExch(&d_scan_flag[bid], 1);
            int excl = 0;
            for (int p = bid - 1; p >= 0; ) {
                int f;
                do { f = atomicAdd(&d_scan_flag[p], 0); } while (f == 0);
                if (f == 2) { excl += atomicAdd(&d_scan_inc[p], 0); break; }
                excl += atomicAdd(&d_scan_agg[p], 0);
                p--;
            }
            d_scan_inc[bid] = excl + block_tot;
            __threadfence();
            atomicExch(&d_scan_flag[bid], 2);
            excl_sh = excl;
        }
        __syncthreads();
        const int add = excl_sh + thr_excl;

        if (base + 15 < n) {
            #pragma unroll
            for (int j = 0; j < 4; j++) {
                int4 qv; qv.x = v[4*j] + add; qv.y = v[4*j+1] + add; qv.z = v[4*j+2] + add; qv.w = v[4*j+3] + add;
                *(int4*)(d_cnt + base + 4 * j) = qv;
            }
        } else {
            #pragma unroll
            for (int j = 0; j < 16; j++) if (base + j < n) d_cnt[base + j] = v[j] + add;
        }
        __syncthreads();
        if (t == 0) { __threadfence(); atomicAdd(&d_scan_done, 1); }
    }

    if (t == 0) {
        while (atomicAdd(&d_scan_done, 0) < nchunk) { }
    }
    __syncthreads();
    __threadfence();

    for (int i = bid * 256 + t; i < E; i += gridDim.x * 256) {
        int tg = eindex[E + i];
        int pos = atomicAdd(&d_cnt[tg], 1);
        d_sorted[pos] = i;
    }
}

// ============ launch 5: finalize ============
__global__ void finalize_kernel(const float* __restrict__ x, float* __restrict__ out, int n) {
    int i = blockIdx.x * blockDim.x + threadIdx.x;
    if (i < n) {
        unsigned u = ((const unsigned*)out)[i];
        unsigned bits = (u & 0x80000000u) ? (u ^ 0x80000000u) : ~u;
        float v = __uint_as_float(bits);
        if (isinf(v)) v = 0.0f;
        out[i] = v + x[i];
    }
}

// ============ launch 4: persistent edge kernel ============
__global__ void __launch_bounds__(NTHR, 2)
edge_kernel(const float* __restrict__ x,
            const float* __restrict__ eweight,
            const int* __restrict__ eindex,
            const float* __restrict__ w1,
            const float* __restrict__ w2,
            const float* __restrict__ w3,
            const float* __restrict__ g1, const float* __restrict__ b1,
            const float* __restrict__ g2, const float* __restrict__ b2,
            const float* __restrict__ g3, const float* __restrict__ b3,
            float* __restrict__ out, int E, int ntiles)
{
    extern __shared__ float sm[];
    uint2* w1p = (uint2*)(sm + OFF_W1P);
    uint2* w2p = (uint2*)(sm + OFF_W2P);
    uint2* w3p = (uint2*)(sm + OFF_W3P);
    uint2* AB  = (uint2*)(sm + OFF_AB);
    float* MS  = sm + OFF_AB;
    float* g1s = sm + OFF_G1;
    float* b1s = sm + OFF_B1;
    float* g2s = sm + OFF_G2;
    float* b2s = sm + OFF_B2;
    float* g3s = sm + OFF_G3;
    float* b3s = sm + OFF_B3;
    int*   tgb[2] = { (int*)(sm + OFF_TG0), (int*)(sm + OFF_TG1) };
    int*   srb[2] = { (int*)(sm + OFF_SR0), (int*)(sm + OFF_SR1) };
    float* ewb[2] = { sm + OFF_EW0, sm + OFF_EW1 };

    const int t    = threadIdx.x;
    const int lane = t & 31;
    const int wid  = t >> 5;
    const int stride = gridDim.x;

    // ---- stage permuted packed weights ONCE ----
    for (int i = t; i < 4096; i += NTHR) {            // w1: kt 0..15, q 0..3, c 0..63
        int kt = i >> 8, q = (i >> 6) & 3, c = i & 63;
        int k = (kt < 8) ? kcol64(kt, q) : 64 + kcol64(kt - 8, q);
        const float* row = w1 + c * TWO_H + k;
        w1p[(kt*4 + q) * WPS + c] = make_uint2(f2tf32(__ldg(row)), f2tf32(__ldg(row + 1)));
    }
    for (int i = t; i < 2048; i += NTHR) {            // w2/w3: kt 0..7, q, c
        int kt = i >> 8, q = (i >> 6) & 3, c = i & 63;
        int k = kcol64(kt, q);
        const float* r2 = w2 + c * HID + k;
        const float* r3 = w3 + c * HID + k;
        w2p[(kt*4 + q) * WPS + c] = make_uint2(f2tf32(__ldg(r2)), f2tf32(__ldg(r2 + 1)));
        w3p[(kt*4 + q) * WPS + c] = make_uint2(f2tf32(__ldg(r3)), f2tf32(__ldg(r3 + 1)));
    }
    if (t < 128) { g1s[t] = g1[t]; b1s[t] = b1[t]; }
    else if (t < 192) {
        int u = t - 128;
        g2s[u] = g2[u]; b2s[u] = b2[u]; g3s[u] = g3[u]; b3s[u] = b3[u];
    }

    int   p_tgt = -1, p_src = 0;
    float p_ew  = 0.f;
    #define LOAD_META(TL)                                            \
        do {                                                         \
            p_tgt = -1; p_src = 0; p_ew = 0.f;                       \
            if (t < TILE && (TL) < ntiles) {                         \
                int ge = (TL) * TILE + t;                            \
                if (ge < E) {                                        \
                    int eid = d_sorted[ge];                          \
                    p_tgt = eindex[E + eid];                         \
                    p_src = eindex[eid];                             \
                    p_ew  = eweight[eid];                            \
                }                                                    \
            }                                                        \
        } while (0)

    const int tile0 = blockIdx.x;
    LOAD_META(tile0);
    if (t < TILE) { tgb[0][t] = p_tgt; srb[0][t] = p_src; ewb[0][t] = p_ew; }
    LOAD_META(tile0 + stride);

    const int grp  = lane >> 2;
    const int q    = lane & 3;
    const int r_lo = wid * 16 + grp;
    const int r_hi = r_lo + 8;
    const int rp   = wid * 8 + grp;

    int par = 0;
    for (int tile = tile0; tile < ntiles; tile += stride, par ^= 1) {
        __syncthreads();

        if (t < TILE) { tgb[par^1][t] = p_tgt; srb[par^1][t] = p_src; ewb[par^1][t] = p_ew; }
        LOAD_META(tile + 2 * stride);

        const int*   tgs = tgb[par];
        const int*   srs = srb[par];
        const float* ews = ewb[par];

        // ---- gather with lane-contiguous columns: float4 at col 16f+4q ----
        float mlo[32], mhi[32];
        const int tg_lo = tgs[r_lo], tg_hi = tgs[r_hi];
        float4 xi_lo[4];
        {
            if (tg_lo >= 0) {
                const float4* xi = (const float4*)(x + (size_t)tg_lo * HID) + q;
                const float4* xj = (const float4*)(x + (size_t)srs[r_lo] * HID) + q;
                float w = ews[r_lo];
                #pragma unroll
                for (int f = 0; f < 4; f++) {
                    float4 vi = __ldg(xi + 4 * f);
                    float4 vj = __ldg(xj + 4 * f);
                    xi_lo[f] = vi;
                    mlo[4*f+0] = vi.x; mlo[4*f+1] = vi.y; mlo[4*f+2] = vi.z; mlo[4*f+3] = vi.w;
                    mlo[16+4*f+0] = w * (vj.x - vi.x);
                    mlo[16+4*f+1] = w * (vj.y - vi.y);
                    mlo[16+4*f+2] = w * (vj.z - vi.z);
                    mlo[16+4*f+3] = w * (vj.w - vi.w);
                }
            } else {
                #pragma unroll
                for (int tt = 0; tt < 32; tt++) mlo[tt] = 0.0f;
                #pragma unroll
                for (int f = 0; f < 4; f++) xi_lo[f] = make_float4(0.f,0.f,0.f,0.f);
            }
        }
        {
            if (tg_hi >= 0) {
                const bool same = (tg_hi == tg_lo);
                const float4* xi = (const float4*)(x + (size_t)tg_hi * HID) + q;
                const float4* xj = (const float4*)(x + (size_t)srs[r_hi] * HID) + q;
                float w = ews[r_hi];
                #pragma unroll
                for (int f = 0; f < 4; f++) {
                    float4 vi = same ? xi_lo[f] : __ldg(xi + 4 * f);
                    float4 vj = __ldg(xj + 4 * f);
                    mhi[4*f+0] = vi.x; mhi[4*f+1] = vi.y; mhi[4*f+2] = vi.z; mhi[4*f+3] = vi.w;
                    mhi[16+4*f+0] = w * (vj.x - vi.x);
                    mhi[16+4*f+1] = w * (vj.y - vi.y);
                    mhi[16+4*f+2] = w * (vj.z - vi.z);
                    mhi[16+4*f+3] = w * (vj.w - vi.w);
                }
            } else {
                #pragma unroll
                for (int tt = 0; tt < 32; tt++) mhi[tt] = 0.0f;
            }
        }

        // ---- LN1 in registers (quad covers full 128-col row) ----
        {
            float s_lo = 0.f, q_lo = 0.f, s_hi = 0.f, q_hi = 0.f;
            #pragma unroll
            for (int tt = 0; tt < 32; tt++) {
                s_lo += mlo[tt]; q_lo += mlo[tt] * mlo[tt];
                s_hi += mhi[tt]; q_hi += mhi[tt] * mhi[tt];
            }
            #pragma unroll
            for (int o = 1; o <= 2; o <<= 1) {
                s_lo += __shfl_xor_sync(0xffffffffu, s_lo, o);
                q_lo += __shfl_xor_sync(0xffffffffu, q_lo, o);
                s_hi += __shfl_xor_sync(0xffffffffu, s_hi, o);
                q_hi += __shfl_xor_sync(0xffffffffu, q_hi, o);
            }
            float mu_lo = s_lo * (1.0f / 128.0f);
            float mu_hi = s_hi * (1.0f / 128.0f);
            float r_l   = rsqrtf(fmaxf(q_lo * (1.0f / 128.0f) - mu_lo * mu_lo, 0.0f) + EPSF);
            float r_h   = rsqrtf(fmaxf(q_hi * (1.0f / 128.0f) - mu_hi * mu_hi, 0.0f) + EPSF);
            #pragma unroll
            for (int f = 0; f < 4; f++) {
                float4 ga = *(const float4*)(g1s + 16*f + 4*q);
                float4 ba = *(const float4*)(b1s + 16*f + 4*q);
                float4 gb = *(const float4*)(g1s + 64 + 16*f + 4*q);
                float4 bb = *(const float4*)(b1s + 64 + 16*f + 4*q);
                const float* gpa = (const float*)&ga;  const float* bpa = (const float*)&ba;
                const float* gpb = (const float*)&gb;  const float* bpb = (const float*)&bb;
                #pragma unroll
                for (int j = 0; j < 4; j++) {
                    float h0 = (mlo[4*f+j] - mu_lo) * r_l * gpa[j] + bpa[j];
                    float h1 = (mhi[4*f+j] - mu_hi) * r_h * gpa[j] + bpa[j];
                    h0 = h0 > 0.f ? h0 : SLOPEF * h0;
                    h1 = h1 > 0.f ? h1 : SLOPEF * h1;
                    mlo[4*f+j] = __uint_as_float(f2tf32(h0));
                    mhi[4*f+j] = __uint_as_float(f2tf32(h1));
                    float d0 = (mlo[16+4*f+j] - mu_lo) * r_l * gpb[j] + bpb[j];
                    float d1 = (mhi[16+4*f+j] - mu_hi) * r_h * gpb[j] + bpb[j];
                    d0 = d0 > 0.f ? d0 : SLOPEF * d0;
                    d1 = d1 > 0.f ? d1 : SLOPEF * d1;
                    mlo[16+4*f+j] = __uint_as_float(f2tf32(d0));
                    mhi[16+4*f+j] = __uint_as_float(f2tf32(d1));
                }
            }
        }

        float acc[8][4];

        // ===== GEMM1 (A from registers; k-permutation matches staging) =====
        #pragma unroll
        for (int nt = 0; nt < 8; nt++)
            #pragma unroll
            for (int j = 0; j < 4; j++) acc[nt][j] = 0.0f;
        #pragma unroll
        for (int kt = 0; kt < 16; kt++) {
            uint32_t a0 = __float_as_uint(mlo[2 * kt]);
            uint32_t a1 = __float_as_uint(mhi[2 * kt]);
            uint32_t a2 = __float_as_uint(mlo[2 * kt + 1]);
            uint32_t a3 = __float_as_uint(mhi[2 * kt + 1]);
            const uint2* wrow = w1p + (kt * 4 + q) * WPS + grp;
            #pragma unroll
            for (int nt = 0; nt < 8; nt++) {
                uint2 bb = wrow[nt * 8];
                mma_tf32(acc[nt], a0, a1, a2, a3, bb.x, bb.y);
            }
        }

        // ---- LN2 -> AB (column-indexed row-pair packing) ----
        {
            float s_lo = 0.f, q_lo = 0.f, s_hi = 0.f, q_hi = 0.f;
            #pragma unroll
            for (int nt = 0; nt < 8; nt++) {
                s_lo += acc[nt][0] + acc[nt][1];
                q_lo += acc[nt][0]*acc[nt][0] + acc[nt][1]*acc[nt][1];
                s_hi += acc[nt][2] + acc[nt][3];
                q_hi += acc[nt][2]*acc[nt][2] + acc[nt][3]*acc[nt][3];
            }
            #pragma unroll
            for (int o = 1; o <= 2; o <<= 1) {
                s_lo += __shfl_xor_sync(0xffffffffu, s_lo, o);
                q_lo += __shfl_xor_sync(0xffffffffu, q_lo, o);
                s_hi += __shfl_xor_sync(0xffffffffu, s_hi, o);
                q_hi += __shfl_xor_sync(0xffffffffu, q_hi, o);
            }
            float mu_lo = s_lo * (1.0f/64.0f);
            float mu_hi = s_hi * (1.0f/64.0f);
            float r_l   = rsqrtf(fmaxf(q_lo * (1.0f/64.0f) - mu_lo*mu_lo, 0.0f) + EPSF);
            float r_h   = rsqrtf(fmaxf(q_hi * (1.0f/64.0f) - mu_hi*mu_hi, 0.0f) + EPSF);

            #pragma unroll
            for (int nt = 0; nt < 8; nt++) {
                int c0 = nt * 8 + 2 * q;
                float2 g = *(float2*)(g2s + c0);
                float2 b = *(float2*)(b2s + c0);
                float h0 = (acc[nt][0] - mu_lo) * r_l * g.x + b.x;
                float h1 = (acc[nt][1] - mu_lo) * r_l * g.y + b.y;
                float h2 = (acc[nt][2] - mu_hi) * r_h * g.x + b.x;
                float h3 = (acc[nt][3] - mu_hi) * r_h * g.y + b.y;
                h0 = h0 > 0.f ? h0 : SLOPEF * h0;
                h1 = h1 > 0.f ? h1 : SLOPEF * h1;
                h2 = h2 > 0.f ? h2 : SLOPEF * h2;
                h3 = h3 > 0.f ? h3 : SLOPEF * h3;
                uint4 pk = make_uint4(f2tf32(h0), f2tf32(h2), f2tf32(h1), f2tf32(h3));
                *(uint4*)(AB + rp * APS2 + c0) = pk;
            }
        }
        __syncwarp();

        // ===== GEMM2 (A: single LDS.128 per kt via permuted columns) =====
        #pragma unroll
        for (int nt = 0; nt < 8; nt++)
            #pragma unroll
            for (int j = 0; j < 4; j++) acc[nt][j] = 0.0f;
        {
            const uint2* Ab = AB + rp * APS2;
            #pragma unroll
            for (int kt = 0; kt < 8; kt++) {
                int k0 = kcol64(kt, q);
                uint4 av = *(const uint4*)(Ab + k0);
                const uint2* wrow = w2p + (kt * 4 + q) * WPS + grp;
                #pragma unroll
                for (int nt = 0; nt < 8; nt++) {
                    uint2 bb = wrow[nt * 8];
                    mma_tf32(acc[nt], av.x, av.y, av.z, av.w, bb.x, bb.y);
                }
            }
        }
        __syncwarp();

        // ---- LN3 -> AB ----
        {
            float s_lo = 0.f, q_lo = 0.f, s_hi = 0.f, q_hi = 0.f;
            #pragma unroll
            for (int nt = 0; nt < 8; nt++) {
                s_lo += acc[nt][0] + acc[nt][1];
                q_lo += acc[nt][0]*acc[nt][0] + acc[nt][1]*acc[nt][1];
                s_hi += acc[nt][2] + acc[nt][3];
                q_hi += acc[nt][2]*acc[nt][2] + acc[nt][3]*acc[nt][3];
            }
            #pragma unroll
            for (int o = 1; o <= 2; o <<= 1) {
                s_lo += __shfl_xor_sync(0xffffffffu, s_lo, o);
                q_lo += __shfl_xor_sync(0xffffffffu, q_lo, o);
                s_hi += __shfl_xor_sync(0xffffffffu, s_hi, o);
                q_hi += __shfl_xor_sync(0xffffffffu, q_hi, o);
            }
            float mu_lo = s_lo * (1.0f/64.0f);
            float mu_hi = s_hi * (1.0f/64.0f);
            float r_l   = rsqrtf(fmaxf(q_lo * (1.0f/64.0f) - mu_lo*mu_lo, 0.0f) + EPSF);
            float r_h   = rsqrtf(fmaxf(q_hi * (1.0f/64.0f) - mu_hi*mu_hi, 0.0f) + EPSF);

            #pragma unroll
            for (int nt = 0; nt < 8; nt++) {
                int c0 = nt * 8 + 2 * q;
                float2 g = *(float2*)(g3s + c0);
                float2 b = *(float2*)(b3s + c0);
                float h0 = (acc[nt][0] - mu_lo) * r_l * g.x + b.x;
                float h1 = (acc[nt][1] - mu_lo) * r_l * g.y + b.y;
                float h2 = (acc[nt][2] - mu_hi) * r_h * g.x + b.x;
                float h3 = (acc[nt][3] - mu_hi) * r_h * g.y + b.y;
                h0 = h0 > 0.f ? h0 : SLOPEF * h0;
                h1 = h1 > 0.f ? h1 : SLOPEF * h1;
                h2 = h2 > 0.f ? h2 : SLOPEF * h2;
                h3 = h3 > 0.f ? h3 : SLOPEF * h3;
                uint4 pk = make_uint4(f2tf32(h0), f2tf32(h2), f2tf32(h1), f2tf32(h3));
                *(uint4*)(AB + rp * APS2 + c0) = pk;
            }
        }
        __syncwarp();

        // ===== GEMM3 =====
        #pragma unroll
        for (int nt = 0; nt < 8; nt++)
            #pragma unroll
            for (int j = 0; j < 4; j++) acc[nt][j] = 0.0f;
        {
            const uint2* Ab = AB + rp * APS2;
            #pragma unroll
            for (int kt = 0; kt < 8; kt++) {
                int k0 = kcol64(kt, q);
                uint4 av = *(const uint4*)(Ab + k0);
                const uint2* wrow = w3p + (kt * 4 + q) * WPS + grp;
                #pragma unroll
                for (int nt = 0; nt < 8; nt++) {
                    uint2 bb = wrow[nt * 8];
                    mma_tf32(acc[nt], av.x, av.y, av.z, av.w, bb.x, bb.y);
                }
            }
        }
        __syncwarp();

        // stage this warp's 16 rows into its private MS slab (MSS=66 keeps it inside
        // the warp's own AB slab: 16*66 == 8 row-pairs * 132)
        #pragma unroll
        for (int nt = 0; nt < 8; nt++) {
            int c0 = nt * 8 + 2 * q;
            float* o = MS + r_lo * MSS + c0;
            *(float2*)o             = make_float2(acc[nt][0], acc[nt][1]);
            *(float2*)(o + 8 * MSS) = make_float2(acc[nt][2], acc[nt][3]);
        }
        __syncwarp();

        // ---- warp-local run-aggregated segment-max epilogue ----
        {
            unsigned* outu = (unsigned*)out;
            const int rs = wid * 16;
            #pragma unroll
            for (int half = 0; half < 2; half++) {
                const int c = lane + 32 * half;
                float m = NEG_INF_F;
                int cur = tgs[rs];
                #pragma unroll 4
                for (int r = rs; r < rs + 16; r++) {
                    int tg2 = tgs[r];
                    if (tg2 != cur) {
                        if (cur >= 0) atomicMax(outu + (unsigned)cur * HID + c, fkey(m));
                        cur = tg2;
                        m = NEG_INF_F;
                    }
                    m = fmaxf(m, MS[r * MSS + c]);
                }
                if (cur >= 0) atomicMax(outu + (unsigned)cur * HID + c, fkey(m));
            }
        }
    }
    #undef LOAD_META
}

extern "C" void kernel_launch(void* const* d_in, const int* in_sizes, int n_in,
                              void* d_out, int out_size) {
    const float* x  = (const float*)d_in[0];
    const float* ew = (const float*)d_in[1];
    const int*   ei = (const int*)d_in[2];
    const float* w1 = (const float*)d_in[3];
    const float* w2 = (const float*)d_in[4];
    const float* w3 = (const float*)d_in[5];
    const float* g1 = (const float*)d_in[6];
    const float* b1 = (const float*)d_in[7];
    const float* g2 = (const float*)d_in[8];
    const float* b2 = (const float*)d_in[9];
    const float* g3 = (const float*)d_in[10];
    const float* b3 = (const float*)d_in[11];
    float* out = (float*)d_out;

    const int E  = in_sizes[1];
    const int NH = out_size;
    const int N  = NH / HID;
    const int n  = N + 1;
    const int nchunk = (n + SCAN_CHUNK - 1) / SCAN_CHUNK;
    const int ntiles = (E + TILE - 1) / TILE;

    int nsm = 148;
    cudaDeviceGetAttribute(&nsm, cudaDevAttrMultiProcessorCount, 0);
    int nblocks = 2 * nsm;
    if (nblocks > ntiles) nblocks = ntiles;
    int ssblocks = 4 * nsm;

    cudaFuncSetAttribute(edge_kernel, cudaFuncAttributeMaxDynamicSharedMemorySize, SMEM_BYTES);

    int zi_n = (n > NH / 4) ? n : NH / 4;
    zero_init_kernel<<<(zi_n + 255) / 256, 256>>>(n, (uint4*)out, NH / 4);       // #1
    hist_kernel<<<(E + 255) / 256, 256>>>(ei, E);                                 // #2
    scan_scatter_kernel<<<ssblocks, 256>>>(ei, E, n, nchunk);                     // #3
    edge_kernel<<<nblocks, NTHR, SMEM_BYTES>>>(                                   // #4 (profiled)
        x, ew, ei, w1, w2, w3, g1, b1, g2, b2, g3, b3, out, E, ntiles);
    finalize_kernel<<<(NH + 255) / 256, 256>>>(x, out, NH);                       // #5
}

// round 15
// speedup vs baseline: 1.8098x; 1.3280x over previous
#include <cuda_runtime.h>
#include <math.h>
#include <stdint.h>

#define HID     64
#define TWO_H   128
#define TILE    128
#define NTHR    256
#define EPSF    1e-5f
#define SLOPEF  0.2f

#define WPS     68     // packed weight row stride (uint2 units) — conflict-free B reads
#define APS2    40     // packed activation row stride (uint2 units) — conflict-free uint4 reads
#define MSS     66     // message staging row stride (floats)

// shared memory layout (float offsets)
#define OFF_W1P 0        // 32 x 68 uint2 = 4352 floats (f16x2 pairs)
#define OFF_W2P 4352     // 16 x 68 uint2 = 2176 floats
#define OFF_W3P 6528     // 2176 floats
#define OFF_AB  8704     // 64 x 40 uint2 = 5120 floats
#define OFF_MS  13824    // 128 x 66 = 8448 floats (separate, no overlay)
#define OFF_G1  22272
#define OFF_B1  22400
#define OFF_G2  22528
#define OFF_B2  22592
#define OFF_G3  22656
#define OFF_B3  22720
#define OFF_TG0 22784
#define OFF_TG1 22912
#define OFF_SR0 23040
#define OFF_SR1 23168
#define OFF_EW0 23296
#define OFF_EW1 23424
#define SMEM_FLOATS 23552
#define SMEM_BYTES  (SMEM_FLOATS * 4)   // 94,208 B -> 2 blocks/SM

// -------- sort scratch --------
#define MAXN 262145
#define MAXE 1048576
#define SCAN_CHUNK 4096
#define MAXCHUNK 128
__device__ int d_cnt[MAXN + 1];
__device__ int d_sorted[MAXE];
__device__ int d_scan_flag[MAXCHUNK];
__device__ int d_scan_agg[MAXCHUNK];
__device__ int d_scan_inc[MAXCHUNK];
__device__ int d_scan_done;

__device__ __forceinline__ unsigned fkey(float v) {
    unsigned u = __float_as_uint(v);
    return u ^ (unsigned)(((int)u >> 31) | 0x80000000);
}
#define KEY_NEG_INF 0x007FFFFFu
#define NEG_INF_F   __int_as_float(0xFF800000)

// pack two floats to f16x2: d = {hi in upper half, lo in lower half}
__device__ __forceinline__ uint32_t hf2(float hi, float lo) {
    uint32_t r;
    asm("cvt.rn.f16x2.f32 %0, %1, %2;" : "=r"(r) : "f"(hi), "f"(lo));
    return r;
}

__device__ __forceinline__ void mma_f16(float acc[4],
                                        uint32_t a0, uint32_t a1, uint32_t a2, uint32_t a3,
                                        uint32_t b0, uint32_t b1) {
    asm volatile(
        "mma.sync.aligned.m16n8k16.row.col.f32.f16.f16.f32 "
        "{%0,%1,%2,%3}, {%4,%5,%6,%7}, {%8,%9}, {%0,%1,%2,%3};"
        : "+f"(acc[0]), "+f"(acc[1]), "+f"(acc[2]), "+f"(acc[3])
        : "r"(a0), "r"(a1), "r"(a2), "r"(a3), "r"(b0), "r"(b1));
}

// ============ prep kernels ============
__global__ void zero_init_kernel(int n, uint4* __restrict__ out, int n4) {
    int i = blockIdx.x * blockDim.x + threadIdx.x;
    if (i < n) d_cnt[i] = 0;
    if (i < MAXCHUNK) d_scan_flag[i] = 0;
    if (i == MAXCHUNK) d_scan_done = 0;
    if (i < n4) out[i] = make_uint4(KEY_NEG_INF, KEY_NEG_INF, KEY_NEG_INF, KEY_NEG_INF);
}

__global__ void hist_kernel(const int* __restrict__ eindex, int E) {
    int i = blockIdx.x * blockDim.x + threadIdx.x;
    if (i < E) atomicAdd(&d_cnt[eindex[E + i] + 1], 1);
}

__global__ void __launch_bounds__(256)
scan_scatter_kernel(const int* __restrict__ eindex, int E, int n, int nchunk) {
    const int t = threadIdx.x, lane = t & 31, w = t >> 5;
    const int bid = blockIdx.x;

    if (bid < nchunk) {
        __shared__ int warp_tot[8];
        __shared__ int excl_sh;
        const int base = bid * SCAN_CHUNK + t * 16;

        int v[16];
        if (base + 15 < n) {
            #pragma unroll
            for (int j = 0; j < 4; j++) {
                int4 qv = *(const int4*)(d_cnt + base + 4 * j);
                v[4*j] = qv.x; v[4*j+1] = qv.y; v[4*j+2] = qv.z; v[4*j+3] = qv.w;
            }
        } else {
            #pragma unroll
            for (int j = 0; j < 16; j++) v[j] = (base + j < n) ? d_cnt[base + j] : 0;
        }
        #pragma unroll
        for (int j = 1; j < 16; j++) v[j] += v[j - 1];

        int s = v[15];
        #pragma unroll
        for (int o = 1; o < 32; o <<= 1) {
            int u = __shfl_up_sync(0xffffffffu, s, o);
            if (lane >= o) s += u;
        }
        if (lane == 31) warp_tot[w] = s;
        __syncthreads();
        if (w == 0) {
            int ws = (lane < 8) ? warp_tot[lane] : 0;
            #pragma unroll
            for (int o = 1; o < 8; o <<= 1) {
                int u = __shfl_up_sync(0xffffffffu, ws, o);
                if (lane >= o) ws += u;
            }
            if (lane < 8) warp_tot[lane] = ws;
        }
        __syncthreads();
        const int block_tot = warp_tot[7];
        const int thr_excl  = (s - v[15]) + (w > 0 ? warp_tot[w - 1] : 0);

        if (t == 0) {
            d_scan_agg[bid] = block_tot;
            __threadfence();
            atomicExch(&d_scan_flag[bid], 1);
            int excl = 0;
            for (int p = bid - 1; p >= 0; ) {
                int f;
                do { f = atomicAdd(&d_scan_flag[p], 0); } while (f == 0);
                if (f == 2) { excl += atomicAdd(&d_scan_inc[p], 0); break; }
                excl += atomicAdd(&d_scan_agg[p], 0);
                p--;
            }
            d_scan_inc[bid] = excl + block_tot;
            __threadfence();
            atomicExch(&d_scan_flag[bid], 2);
            excl_sh = excl;
        }
        __syncthreads();
        const int add = excl_sh + thr_excl;

        if (base + 15 < n) {
            #pragma unroll
            for (int j = 0; j < 4; j++) {
                int4 qv; qv.x = v[4*j] + add; qv.y = v[4*j+1] + add; qv.z = v[4*j+2] + add; qv.w = v[4*j+3] + add;
                *(int4*)(d_cnt + base + 4 * j) = qv;
            }
        } else {
            #pragma unroll
            for (int j = 0; j < 16; j++) if (base + j < n) d_cnt[base + j] = v[j] + add;
        }
        __syncthreads();
        if (t == 0) { __threadfence(); atomicAdd(&d_scan_done, 1); }
    }

    if (t == 0) {
        while (atomicAdd(&d_scan_done, 0) < nchunk) { }
    }
    __syncthreads();
    __threadfence();

    for (int i = bid * 256 + t; i < E; i += gridDim.x * 256) {
        int tg = eindex[E + i];
        int pos = atomicAdd(&d_cnt[tg], 1);
        d_sorted[pos] = i;
    }
}

__global__ void finalize_kernel(const float* __restrict__ x, float* __restrict__ out, int n) {
    int i = blockIdx.x * blockDim.x + threadIdx.x;
    if (i < n) {
        unsigned u = ((const unsigned*)out)[i];
        unsigned bits = (u & 0x80000000u) ? (u ^ 0x80000000u) : ~u;
        float v = __uint_as_float(bits);
        if (isinf(v)) v = 0.0f;
        out[i] = v + x[i];
    }
}

// ============ launch 4: persistent fp16 edge kernel ============
__global__ void __launch_bounds__(NTHR, 2)
edge_kernel(const float* __restrict__ x,
            const float* __restrict__ eweight,
            const int* __restrict__ eindex,
            const float* __restrict__ w1,
            const float* __restrict__ w2,
            const float* __restrict__ w3,
            const float* __restrict__ g1, const float* __restrict__ b1,
            const float* __restrict__ g2, const float* __restrict__ b2,
            const float* __restrict__ g3, const float* __restrict__ b3,
            float* __restrict__ out, int E, int ntiles)
{
    extern __shared__ float sm[];
    uint2* w1p = (uint2*)(sm + OFF_W1P);
    uint2* w2p = (uint2*)(sm + OFF_W2P);
    uint2* w3p = (uint2*)(sm + OFF_W3P);
    uint2* AB  = (uint2*)(sm + OFF_AB);
    float* MS  = sm + OFF_MS;
    float* g1s = sm + OFF_G1;
    float* b1s = sm + OFF_B1;
    float* g2s = sm + OFF_G2;
    float* b2s = sm + OFF_B2;
    float* g3s = sm + OFF_G3;
    float* b3s = sm + OFF_B3;
    int*   tgb[2] = { (int*)(sm + OFF_TG0), (int*)(sm + OFF_TG1) };
    int*   srb[2] = { (int*)(sm + OFF_SR0), (int*)(sm + OFF_SR1) };
    float* ewb[2] = { sm + OFF_EW0, sm + OFF_EW1 };

    const int t    = threadIdx.x;
    const int lane = t & 31;
    const int wid  = t >> 5;
    const int stride = gridDim.x;

    // ---- stage packed fp16 weights ONCE ----
    // wp[(kt*4+q)*WPS + c] = { hf2(W[c][K0+1],W[c][K0]), hf2(W[c][K0+3],W[c][K0+2]) }, K0=16kt+4q
    for (int i = t; i < 2048; i += NTHR) {            // w1: kt 0..7, q 0..3, c 0..63
        int kt = i >> 8, q = (i >> 6) & 3, c = i & 63;
        float4 v = *(const float4*)(w1 + c * TWO_H + 16 * kt + 4 * q);
        w1p[(kt*4 + q) * WPS + c] = make_uint2(hf2(v.y, v.x), hf2(v.w, v.z));
    }
    for (int i = t; i < 1024; i += NTHR) {            // w2/w3: kt 0..3, q, c
        int kt = i >> 8, q = (i >> 6) & 3, c = i & 63;
        float4 v2 = *(const float4*)(w2 + c * HID + 16 * kt + 4 * q);
        float4 v3 = *(const float4*)(w3 + c * HID + 16 * kt + 4 * q);
        w2p[(kt*4 + q) * WPS + c] = make_uint2(hf2(v2.y, v2.x), hf2(v2.w, v2.z));
        w3p[(kt*4 + q) * WPS + c] = make_uint2(hf2(v3.y, v3.x), hf2(v3.w, v3.z));
    }
    if (t < 128) { g1s[t] = g1[t]; b1s[t] = b1[t]; }
    else if (t < 192) {
        int u = t - 128;
        g2s[u] = g2[u]; b2s[u] = b2[u]; g3s[u] = g3[u]; b3s[u] = b3[u];
    }

    int   p_tgt = -1, p_src = 0;
    float p_ew  = 0.f;
    #define LOAD_META(TL)                                            \
        do {                                                         \
            p_tgt = -1; p_src = 0; p_ew = 0.f;                       \
            if (t < TILE && (TL) < ntiles) {                         \
                int ge = (TL) * TILE + t;                            \
                if (ge < E) {                                        \
                    int eid = d_sorted[ge];                          \
                    p_tgt = eindex[E + eid];                         \
                    p_src = eindex[eid];                             \
                    p_ew  = eweight[eid];                            \
                }                                                    \
            }                                                        \
        } while (0)

    const int tile0 = blockIdx.x;
    LOAD_META(tile0);
    if (t < TILE) { tgb[0][t] = p_tgt; srb[0][t] = p_src; ewb[0][t] = p_ew; }
    LOAD_META(tile0 + stride);

    const int grp  = lane >> 2;
    const int q    = lane & 3;
    const int r_lo = wid * 16 + grp;
    const int r_hi = r_lo + 8;
    const int rp   = wid * 8 + grp;

    int par = 0;
    for (int tile = tile0; tile < ntiles; tile += stride, par ^= 1) {
        __syncthreads();   // meta buf visible; prev epilogue MS reads done

        if (t < TILE) { tgb[par^1][t] = p_tgt; srb[par^1][t] = p_src; ewb[par^1][t] = p_ew; }
        LOAD_META(tile + 2 * stride);

        const int*   tgs = tgb[par];
        const int*   srs = srb[par];
        const float* ews = ewb[par];

        // ---- gather with lane-contiguous columns (float4 at col 16f+4q) ----
        float mlo[32], mhi[32];
        const int tg_lo = tgs[r_lo], tg_hi = tgs[r_hi];
        float4 xi_lo[4];
        {
            if (tg_lo >= 0) {
                const float4* xi = (const float4*)(x + (size_t)tg_lo * HID) + q;
                const float4* xj = (const float4*)(x + (size_t)srs[r_lo] * HID) + q;
                float w = ews[r_lo];
                #pragma unroll
                for (int f = 0; f < 4; f++) {
                    float4 vi = __ldg(xi + 4 * f);
                    float4 vj = __ldg(xj + 4 * f);
                    xi_lo[f] = vi;
                    mlo[4*f+0] = vi.x; mlo[4*f+1] = vi.y; mlo[4*f+2] = vi.z; mlo[4*f+3] = vi.w;
                    mlo[16+4*f+0] = w * (vj.x - vi.x);
                    mlo[16+4*f+1] = w * (vj.y - vi.y);
                    mlo[16+4*f+2] = w * (vj.z - vi.z);
                    mlo[16+4*f+3] = w * (vj.w - vi.w);
                }
            } else {
                #pragma unroll
                for (int tt = 0; tt < 32; tt++) mlo[tt] = 0.0f;
                #pragma unroll
                for (int f = 0; f < 4; f++) xi_lo[f] = make_float4(0.f,0.f,0.f,0.f);
            }
        }
        {
            if (tg_hi >= 0) {
                const bool same = (tg_hi == tg_lo);
                const float4* xi = (const float4*)(x + (size_t)tg_hi * HID) + q;
                const float4* xj = (const float4*)(x + (size_t)srs[r_hi] * HID) + q;
                float w = ews[r_hi];
                #pragma unroll
                for (int f = 0; f < 4; f++) {
                    float4 vi = same ? xi_lo[f] : __ldg(xi + 4 * f);
                    float4 vj = __ldg(xj + 4 * f);
                    mhi[4*f+0] = vi.x; mhi[4*f+1] = vi.y; mhi[4*f+2] = vi.z; mhi[4*f+3] = vi.w;
                    mhi[16+4*f+0] = w * (vj.x - vi.x);
                    mhi[16+4*f+1] = w * (vj.y - vi.y);
                    mhi[16+4*f+2] = w * (vj.z - vi.z);
                    mhi[16+4*f+3] = w * (vj.w - vi.w);
                }
            } else {
                #pragma unroll
                for (int tt = 0; tt < 32; tt++) mhi[tt] = 0.0f;
            }
        }

        // ---- LN1 (width 128) in registers; keep fp32, pack to f16 in GEMM1 ----
        {
            float s_lo = 0.f, q_lo = 0.f, s_hi = 0.f, q_hi = 0.f;
            #pragma unroll
            for (int tt = 0; tt < 32; tt++) {
                s_lo += mlo[tt]; q_lo += mlo[tt] * mlo[tt];
                s_hi += mhi[tt]; q_hi += mhi[tt] * mhi[tt];
            }
            #pragma unroll
            for (int o = 1; o <= 2; o <<= 1) {
                s_lo += __shfl_xor_sync(0xffffffffu, s_lo, o);
                q_lo += __shfl_xor_sync(0xffffffffu, q_lo, o);
                s_hi += __shfl_xor_sync(0xffffffffu, s_hi, o);
                q_hi += __shfl_xor_sync(0xffffffffu, q_hi, o);
            }
            float mu_lo = s_lo * (1.0f / 128.0f);
            float mu_hi = s_hi * (1.0f / 128.0f);
            float r_l   = rsqrtf(fmaxf(q_lo * (1.0f / 128.0f) - mu_lo * mu_lo, 0.0f) + EPSF);
            float r_h   = rsqrtf(fmaxf(q_hi * (1.0f / 128.0f) - mu_hi * mu_hi, 0.0f) + EPSF);
            // logical col of mlo[4kt+j] is 16kt+4q+j for kt 0..7 (both halves)
            #pragma unroll
            for (int kt = 0; kt < 8; kt++) {
                int c0 = 16 * kt + 4 * q;
                #pragma unroll
                for (int j = 0; j < 4; j++) {
                    float g = g1s[c0 + j], b = b1s[c0 + j];
                    float h0 = (mlo[4*kt+j] - mu_lo) * r_l * g + b;
                    float h1 = (mhi[4*kt+j] - mu_hi) * r_h * g + b;
                    mlo[4*kt+j] = h0 > 0.f ? h0 : SLOPEF * h0;
                    mhi[4*kt+j] = h1 > 0.f ? h1 : SLOPEF * h1;
                }
            }
        }

        float acc[8][4];

        // ===== GEMM1: K=128, 8 fp16 MMA steps (A packed on the fly) =====
        #pragma unroll
        for (int nt = 0; nt < 8; nt++)
            #pragma unroll
            for (int j = 0; j < 4; j++) acc[nt][j] = 0.0f;
        #pragma unroll
        for (int kt = 0; kt < 8; kt++) {
            uint32_t a0 = hf2(mlo[4*kt+1], mlo[4*kt]);
            uint32_t a1 = hf2(mhi[4*kt+1], mhi[4*kt]);
            uint32_t a2 = hf2(mlo[4*kt+3], mlo[4*kt+2]);
            uint32_t a3 = hf2(mhi[4*kt+3], mhi[4*kt+2]);
            const uint2* wrow = w1p + (kt * 4 + q) * WPS + grp;
            #pragma unroll
            for (int nt = 0; nt < 8; nt++) {
                uint2 bb = wrow[nt * 8];
                mma_f16(acc[nt], a0, a1, a2, a3, bb.x, bb.y);
            }
        }

        // ---- LN2 -> AB (pair-indexed f16x2; pair p = 4nt+q) ----
        {
            float s_lo = 0.f, q_lo = 0.f, s_hi = 0.f, q_hi = 0.f;
            #pragma unroll
            for (int nt = 0; nt < 8; nt++) {
                s_lo += acc[nt][0] + acc[nt][1];
                q_lo += acc[nt][0]*acc[nt][0] + acc[nt][1]*acc[nt][1];
                s_hi += acc[nt][2] + acc[nt][3];
                q_hi += acc[nt][2]*acc[nt][2] + acc[nt][3]*acc[nt][3];
            }
            #pragma unroll
            for (int o = 1; o <= 2; o <<= 1) {
                s_lo += __shfl_xor_sync(0xffffffffu, s_lo, o);
                q_lo += __shfl_xor_sync(0xffffffffu, q_lo, o);
                s_hi += __shfl_xor_sync(0xffffffffu, s_hi, o);
                q_hi += __shfl_xor_sync(0xffffffffu, q_hi, o);
            }
            float mu_lo = s_lo * (1.0f/64.0f);
            float mu_hi = s_hi * (1.0f/64.0f);
            float r_l   = rsqrtf(fmaxf(q_lo * (1.0f/64.0f) - mu_lo*mu_lo, 0.0f) + EPSF);
            float r_h   = rsqrtf(fmaxf(q_hi * (1.0f/64.0f) - mu_hi*mu_hi, 0.0f) + EPSF);

            #pragma unroll
            for (int nt = 0; nt < 8; nt++) {
                int c0 = nt * 8 + 2 * q;
                float2 g = *(float2*)(g2s + c0);
                float2 b = *(float2*)(b2s + c0);
                float h0 = (acc[nt][0] - mu_lo) * r_l * g.x + b.x;
                float h1 = (acc[nt][1] - mu_lo) * r_l * g.y + b.y;
                float h2 = (acc[nt][2] - mu_hi) * r_h * g.x + b.x;
                float h3 = (acc[nt][3] - mu_hi) * r_h * g.y + b.y;
                h0 = h0 > 0.f ? h0 : SLOPEF * h0;
                h1 = h1 > 0.f ? h1 : SLOPEF * h1;
                h2 = h2 > 0.f ? h2 : SLOPEF * h2;
                h3 = h3 > 0.f ? h3 : SLOPEF * h3;
                AB[rp * APS2 + 4 * nt + q] = make_uint2(hf2(h1, h0), hf2(h3, h2));
            }
        }
        __syncwarp();

        // ===== GEMM2: K=64, 4 steps; A = one LDS.128 per kt =====
        #pragma unroll
        for (int nt = 0; nt < 8; nt++)
            #pragma unroll
            for (int j = 0; j < 4; j++) acc[nt][j] = 0.0f;
        {
            const uint2* Ab = AB + rp * APS2;
            #pragma unroll
            for (int kt = 0; kt < 4; kt++) {
                uint4 av = *(const uint4*)(Ab + 8 * kt + 2 * q);  // {a0,a1,a2,a3}
                const uint2* wrow = w2p + (kt * 4 + q) * WPS + grp;
                #pragma unroll
                for (int nt = 0; nt < 8; nt++) {
                    uint2 bb = wrow[nt * 8];
                    mma_f16(acc[nt], av.x, av.y, av.z, av.w, bb.x, bb.y);
                }
            }
        }
        __syncwarp();

        // ---- LN3 -> AB ----
        {
            float s_lo = 0.f, q_lo = 0.f, s_hi = 0.f, q_hi = 0.f;
            #pragma unroll
            for (int nt = 0; nt < 8; nt++) {
                s_lo += acc[nt][0] + acc[nt][1];
                q_lo += acc[nt][0]*acc[nt][0] + acc[nt][1]*acc[nt][1];
                s_hi += acc[nt][2] + acc[nt][3];
                q_hi += acc[nt][2]*acc[nt][2] + acc[nt][3]*acc[nt][3];
            }
            #pragma unroll
            for (int o = 1; o <= 2; o <<= 1) {
                s_lo += __shfl_xor_sync(0xffffffffu, s_lo, o);
                q_lo += __shfl_xor_sync(0xffffffffu, q_lo, o);
                s_hi += __shfl_xor_sync(0xffffffffu, s_hi, o);
                q_hi += __shfl_xor_sync(0xffffffffu, q_hi, o);
            }
            float mu_lo = s_lo * (1.0f/64.0f);
            float mu_hi = s_hi * (1.0f/64.0f);
            float r_l   = rsqrtf(fmaxf(q_lo * (1.0f/64.0f) - mu_lo*mu_lo, 0.0f) + EPSF);
            float r_h   = rsqrtf(fmaxf(q_hi * (1.0f/64.0f) - mu_hi*mu_hi, 0.0f) + EPSF);

            #pragma unroll
            for (int nt = 0; nt < 8; nt++) {
                int c0 = nt * 8 + 2 * q;
                float2 g = *(float2*)(g3s + c0);
                float2 b = *(float2*)(b3s + c0);
                float h0 = (acc[nt][0] - mu_lo) * r_l * g.x + b.x;
                float h1 = (acc[nt][1] - mu_lo) * r_l * g.y + b.y;
                float h2 = (acc[nt][2] - mu_hi) * r_h * g.x + b.x;
                float h3 = (acc[nt][3] - mu_hi) * r_h * g.y + b.y;
                h0 = h0 > 0.f ? h0 : SLOPEF * h0;
                h1 = h1 > 0.f ? h1 : SLOPEF * h1;
                h2 = h2 > 0.f ? h2 : SLOPEF * h2;
                h3 = h3 > 0.f ? h3 : SLOPEF * h3;
                AB[rp * APS2 + 4 * nt + q] = make_uint2(hf2(h1, h0), hf2(h3, h2));
            }
        }
        __syncwarp();

        // ===== GEMM3 =====
        #pragma unroll
        for (int nt = 0; nt < 8; nt++)
            #pragma unroll
            for (int j = 0; j < 4; j++) acc[nt][j] = 0.0f;
        {
            const uint2* Ab = AB + rp * APS2;
            #pragma unroll
            for (int kt = 0; kt < 4; kt++) {
                uint4 av = *(const uint4*)(Ab + 8 * kt + 2 * q);
                const uint2* wrow = w3p + (kt * 4 + q) * WPS + grp;
                #pragma unroll
                for (int nt = 0; nt < 8; nt++) {
                    uint2 bb = wrow[nt * 8];
                    mma_f16(acc[nt], av.x, av.y, av.z, av.w, bb.x, bb.y);
                }
            }
        }
        __syncwarp();

        // stage this warp's 16 rows into its MS slab (separate buffer, fp32)
        #pragma unroll
        for (int nt = 0; nt < 8; nt++) {
            int c0 = nt * 8 + 2 * q;
            float* o = MS + r_lo * MSS + c0;
            *(float2*)o             = make_float2(acc[nt][0], acc[nt][1]);
            *(float2*)(o + 8 * MSS) = make_float2(acc[nt][2], acc[nt][3]);
        }
        __syncwarp();

        // ---- warp-local run-aggregated segment-max epilogue ----
        {
            unsigned* outu = (unsigned*)out;
            const int rs = wid * 16;
            #pragma unroll
            for (int half = 0; half < 2; half++) {
                const int c = lane + 32 * half;
                float m = NEG_INF_F;
                int cur = tgs[rs];
                #pragma unroll 4
                for (int r = rs; r < rs + 16; r++) {
                    int tg2 = tgs[r];
                    if (tg2 != cur) {
                        if (cur >= 0) atomicMax(outu + (unsigned)cur * HID + c, fkey(m));
                        cur = tg2;
                        m = NEG_INF_F;
                    }
                    m = fmaxf(m, MS[r * MSS + c]);
                }
                if (cur >= 0) atomicMax(outu + (unsigned)cur * HID + c, fkey(m));
            }
        }
    }
    #undef LOAD_META
}

extern "C" void kernel_launch(void* const* d_in, const int* in_sizes, int n_in,
                              void* d_out, int out_size) {
    const float* x  = (const float*)d_in[0];
    const float* ew = (const float*)d_in[1];
    const int*   ei = (const int*)d_in[2];
    const float* w1 = (const float*)d_in[3];
    const float* w2 = (const float*)d_in[4];
    const float* w3 = (const float*)d_in[5];
    const float* g1 = (const float*)d_in[6];
    const float* b1 = (const float*)d_in[7];
    const float* g2 = (const float*)d_in[8];
    const float* b2 = (const float*)d_in[9];
    const float* g3 = (const float*)d_in[10];
    const float* b3 = (const float*)d_in[11];
    float* out = (float*)d_out;

    const int E  = in_sizes[1];
    const int NH = out_size;
    const int N  = NH / HID;
    const int n  = N + 1;
    const int nchunk = (n + SCAN_CHUNK - 1) / SCAN_CHUNK;
    const int ntiles = (E + TILE - 1) / TILE;

    int nsm = 148;
    cudaDeviceGetAttribute(&nsm, cudaDevAttrMultiProcessorCount, 0);
    int nblocks = 2 * nsm;
    if (nblocks > ntiles) nblocks = ntiles;
    int ssblocks = 4 * nsm;

    cudaFuncSetAttribute(edge_kernel, cudaFuncAttributeMaxDynamicSharedMemorySize, SMEM_BYTES);

    int zi_n = (n > NH / 4) ? n : NH / 4;
    zero_init_kernel<<<(zi_n + 255) / 256, 256>>>(n, (uint4*)out, NH / 4);       // #1
    hist_kernel<<<(E + 255) / 256, 256>>>(ei, E);                                 // #2
    scan_scatter_kernel<<<ssblocks, 256>>>(ei, E, n, nchunk);                     // #3
    edge_kernel<<<nblocks, NTHR, SMEM_BYTES>>>(                                   // #4 (profiled)
        x, ew, ei, w1, w2, w3, g1, b1, g2, b2, g3, b3, out, E, ntiles);
    finalize_kernel<<<(NH + 255) / 256, 256>>>(x, out, NH);                       // #5
}

// round 16
// speedup vs baseline: 2.0714x; 1.1445x over previous
#include <cuda_runtime.h>
#include <cuda_fp16.h>
#include <math.h>
#include <stdint.h>

#define HID     64
#define TWO_H   128
#define TILE    128
#define NTHR    256
#define EPSF    1e-5f
#define SLOPEF  0.2f

#define WP4     34     // weight row stride in uint4 (paired B-frags); conflict-free LDS.128
#define APS2    40     // packed activation row stride (uint2 units)
#define MS4     34     // f16x2 message staging row stride (uint32 units)

// shared memory layout (float offsets)
#define OFF_W1P 0        // 32 rows x 34 uint4 = 4352 floats
#define OFF_W2P 4352     // 16 x 34 uint4 = 2176
#define OFF_W3P 6528     // 2176
#define OFF_AB  8704     // 64 x 40 uint2 = 5120
#define OFF_MS  13824    // 128 x 34 uint32 = 4352 (f16x2 messages)
#define OFF_G1  18176
#define OFF_B1  18304
#define OFF_G2  18432
#define OFF_B2  18496
#define OFF_G3  18560
#define OFF_B3  18624
#define OFF_TG0 18688
#define OFF_TG1 18816
#define OFF_SR0 18944
#define OFF_SR1 19072
#define OFF_EW0 19200
#define OFF_EW1 19328
#define SMEM_FLOATS 19456
#define SMEM_BYTES  (SMEM_FLOATS * 4)   // 77,824 B -> 2 blocks/SM

// -------- sort scratch --------
#define MAXN 262145
#define MAXE 1048576
#define SCAN_CHUNK 4096
#define MAXCHUNK 128
__device__ int d_cnt[MAXN + 1];
__device__ int d_sorted[MAXE];
__device__ int d_scan_flag[MAXCHUNK];
__device__ int d_scan_agg[MAXCHUNK];
__device__ int d_scan_inc[MAXCHUNK];
__device__ int d_scan_done;

__device__ __forceinline__ unsigned fkey(float v) {
    unsigned u = __float_as_uint(v);
    return u ^ (unsigned)(((int)u >> 31) | 0x80000000);
}
#define KEY_NEG_INF 0x007FFFFFu
#define NEG_INF_F   __int_as_float(0xFF800000)

// pack two floats to f16x2: {hi in upper half, lo in lower half}
__device__ __forceinline__ uint32_t hf2(float hi, float lo) {
    uint32_t r;
    asm("cvt.rn.f16x2.f32 %0, %1, %2;" : "=r"(r) : "f"(hi), "f"(lo));
    return r;
}

__device__ __forceinline__ void mma_f16(float acc[4],
                                        uint32_t a0, uint32_t a1, uint32_t a2, uint32_t a3,
                                        uint32_t b0, uint32_t b1) {
    asm volatile(
        "mma.sync.aligned.m16n8k16.row.col.f32.f16.f16.f32 "
        "{%0,%1,%2,%3}, {%4,%5,%6,%7}, {%8,%9}, {%0,%1,%2,%3};"
        : "+f"(acc[0]), "+f"(acc[1]), "+f"(acc[2]), "+f"(acc[3])
        : "r"(a0), "r"(a1), "r"(a2), "r"(a3), "r"(b0), "r"(b1));
}

// ============ prep kernels ============
__global__ void zero_init_kernel(int n, uint4* __restrict__ out, int n4) {
    int i = blockIdx.x * blockDim.x + threadIdx.x;
    if (i < n) d_cnt[i] = 0;
    if (i < MAXCHUNK) d_scan_flag[i] = 0;
    if (i == MAXCHUNK) d_scan_done = 0;
    if (i < n4) out[i] = make_uint4(KEY_NEG_INF, KEY_NEG_INF, KEY_NEG_INF, KEY_NEG_INF);
}

__global__ void hist_kernel(const int* __restrict__ eindex, int E) {
    int i = blockIdx.x * blockDim.x + threadIdx.x;
    if (i < E) atomicAdd(&d_cnt[eindex[E + i] + 1], 1);
}

__global__ void __launch_bounds__(256)
scan_scatter_kernel(const int* __restrict__ eindex, int E, int n, int nchunk) {
    const int t = threadIdx.x, lane = t & 31, w = t >> 5;
    const int bid = blockIdx.x;

    if (bid < nchunk) {
        __shared__ int warp_tot[8];
        __shared__ int excl_sh;
        const int base = bid * SCAN_CHUNK + t * 16;

        int v[16];
        if (base + 15 < n) {
            #pragma unroll
            for (int j = 0; j < 4; j++) {
                int4 qv = *(const int4*)(d_cnt + base + 4 * j);
                v[4*j] = qv.x; v[4*j+1] = qv.y; v[4*j+2] = qv.z; v[4*j+3] = qv.w;
            }
        } else {
            #pragma unroll
            for (int j = 0; j < 16; j++) v[j] = (base + j < n) ? d_cnt[base + j] : 0;
        }
        #pragma unroll
        for (int j = 1; j < 16; j++) v[j] += v[j - 1];

        int s = v[15];
        #pragma unroll
        for (int o = 1; o < 32; o <<= 1) {
            int u = __shfl_up_sync(0xffffffffu, s, o);
            if (lane >= o) s += u;
        }
        if (lane == 31) warp_tot[w] = s;
        __syncthreads();
        if (w == 0) {
            int ws = (lane < 8) ? warp_tot[lane] : 0;
            #pragma unroll
            for (int o = 1; o < 8; o <<= 1) {
                int u = __shfl_up_sync(0xffffffffu, ws, o);
                if (lane >= o) ws += u;
            }
            if (lane < 8) warp_tot[lane] = ws;
        }
        __syncthreads();
        const int block_tot = warp_tot[7];
        const int thr_excl  = (s - v[15]) + (w > 0 ? warp_tot[w - 1] : 0);

        if (t == 0) {
            d_scan_agg[bid] = block_tot;
            __threadfence();
            atomicExch(&d_scan_flag[bid], 1);
            int excl = 0;
            for (int p = bid - 1; p >= 0; ) {
                int f;
                do { f = atomicAdd(&d_scan_flag[p], 0); } while (f == 0);
                if (f == 2) { excl += atomicAdd(&d_scan_inc[p], 0); break; }
                excl += atomicAdd(&d_scan_agg[p], 0);
                p--;
            }
            d_scan_inc[bid] = excl + block_tot;
            __threadfence();
            atomicExch(&d_scan_flag[bid], 2);
            excl_sh = excl;
        }
        __syncthreads();
        const int add = excl_sh + thr_excl;

        if (base + 15 < n) {
            #pragma unroll
            for (int j = 0; j < 4; j++) {
                int4 qv; qv.x = v[4*j] + add; qv.y = v[4*j+1] + add; qv.z = v[4*j+2] + add; qv.w = v[4*j+3] + add;
                *(int4*)(d_cnt + base + 4 * j) = qv;
            }
        } else {
            #pragma unroll
            for (int j = 0; j < 16; j++) if (base + j < n) d_cnt[base + j] = v[j] + add;
        }
        __syncthreads();
        if (t == 0) { __threadfence(); atomicAdd(&d_scan_done, 1); }
    }

    if (t == 0) {
        while (atomicAdd(&d_scan_done, 0) < nchunk) { }
    }
    __syncthreads();
    __threadfence();

    for (int i = bid * 256 + t; i < E; i += gridDim.x * 256) {
        int tg = eindex[E + i];
        int pos = atomicAdd(&d_cnt[tg], 1);
        d_sorted[pos] = i;
    }
}

__global__ void finalize_kernel(const float* __restrict__ x, float* __restrict__ out, int n) {
    int i = blockIdx.x * blockDim.x + threadIdx.x;
    if (i < n) {
        unsigned u = ((const unsigned*)out)[i];
        unsigned bits = (u & 0x80000000u) ? (u ^ 0x80000000u) : ~u;
        float v = __uint_as_float(bits);
        if (isinf(v)) v = 0.0f;
        out[i] = v + x[i];
    }
}

// ============ launch 4: persistent fp16 edge kernel ============
__global__ void __launch_bounds__(NTHR, 2)
edge_kernel(const float* __restrict__ x,
            const float* __restrict__ eweight,
            const int* __restrict__ eindex,
            const float* __restrict__ w1,
            const float* __restrict__ w2,
            const float* __restrict__ w3,
            const float* __restrict__ g1, const float* __restrict__ b1,
            const float* __restrict__ g2, const float* __restrict__ b2,
            const float* __restrict__ g3, const float* __restrict__ b3,
            float* __restrict__ out, int E, int ntiles)
{
    extern __shared__ float sm[];
    uint4*    w1p4 = (uint4*)(sm + OFF_W1P);
    uint4*    w2p4 = (uint4*)(sm + OFF_W2P);
    uint4*    w3p4 = (uint4*)(sm + OFF_W3P);
    uint2*    AB   = (uint2*)(sm + OFF_AB);
    uint32_t* MS16 = (uint32_t*)(sm + OFF_MS);
    float* g1s = sm + OFF_G1;
    float* b1s = sm + OFF_B1;
    float* g2s = sm + OFF_G2;
    float* b2s = sm + OFF_B2;
    float* g3s = sm + OFF_G3;
    float* b3s = sm + OFF_B3;
    int*   tgb[2] = { (int*)(sm + OFF_TG0), (int*)(sm + OFF_TG1) };
    int*   srb[2] = { (int*)(sm + OFF_SR0), (int*)(sm + OFF_SR1) };
    float* ewb[2] = { sm + OFF_EW0, sm + OFF_EW1 };

    const int t    = threadIdx.x;
    const int lane = t & 31;
    const int wid  = t >> 5;
    const int stride = gridDim.x;

    // ---- stage paired fp16 weights ONCE ----
    // uint4 at row (kt*4+q), idx p*8+g = B-frags for cols {2p*8+g, (2p+1)*8+g}, K0 = 16kt+4q
    {
        uint2* w1p2 = (uint2*)w1p4;
        for (int i = t; i < 2048; i += NTHR) {            // w1: kt 0..7, q, c
            int kt = i >> 8, q = (i >> 6) & 3, c = i & 63;
            float4 v = *(const float4*)(w1 + c * TWO_H + 16 * kt + 4 * q);
            int nt = c >> 3, g = c & 7;
            w1p2[((kt*4 + q)*WP4 + (nt >> 1)*8 + g)*2 + (nt & 1)] =
                make_uint2(hf2(v.y, v.x), hf2(v.w, v.z));
        }
        uint2* w2p2 = (uint2*)w2p4;
        uint2* w3p2 = (uint2*)w3p4;
        for (int i = t; i < 1024; i += NTHR) {            // w2/w3: kt 0..3, q, c
            int kt = i >> 8, q = (i >> 6) & 3, c = i & 63;
            float4 v2 = *(const float4*)(w2 + c * HID + 16 * kt + 4 * q);
            float4 v3 = *(const float4*)(w3 + c * HID + 16 * kt + 4 * q);
            int nt = c >> 3, g = c & 7;
            int idx = ((kt*4 + q)*WP4 + (nt >> 1)*8 + g)*2 + (nt & 1);
            w2p2[idx] = make_uint2(hf2(v2.y, v2.x), hf2(v2.w, v2.z));
            w3p2[idx] = make_uint2(hf2(v3.y, v3.x), hf2(v3.w, v3.z));
        }
    }
    if (t < 128) { g1s[t] = g1[t]; b1s[t] = b1[t]; }
    else if (t < 192) {
        int u = t - 128;
        g2s[u] = g2[u]; b2s[u] = b2[u]; g3s[u] = g3[u]; b3s[u] = b3[u];
    }

    int   p_tgt = -1, p_src = 0;
    float p_ew  = 0.f;
    #define LOAD_META(TL)                                            \
        do {                                                         \
            p_tgt = -1; p_src = 0; p_ew = 0.f;                       \
            if (t < TILE && (TL) < ntiles) {                         \
                int ge = (TL) * TILE + t;                            \
                if (ge < E) {                                        \
                    int eid = d_sorted[ge];                          \
                    p_tgt = eindex[E + eid];                         \
                    p_src = eindex[eid];                             \
                    p_ew  = eweight[eid];                            \
                }                                                    \
            }                                                        \
        } while (0)

    const int tile0 = blockIdx.x;
    LOAD_META(tile0);
    if (t < TILE) { tgb[0][t] = p_tgt; srb[0][t] = p_src; ewb[0][t] = p_ew; }
    LOAD_META(tile0 + stride);

    const int grp  = lane >> 2;
    const int q    = lane & 3;
    const int r_lo = wid * 16 + grp;
    const int r_hi = r_lo + 8;
    const int rp   = wid * 8 + grp;

    int par = 0;
    for (int tile = tile0; tile < ntiles; tile += stride, par ^= 1) {
        __syncthreads();   // meta buf visible; prev MS reads done; staging visible (1st iter)

        if (t < TILE) { tgb[par^1][t] = p_tgt; srb[par^1][t] = p_src; ewb[par^1][t] = p_ew; }
        LOAD_META(tile + 2 * stride);

        const int*   tgs = tgb[par];
        const int*   srs = srb[par];
        const float* ews = ewb[par];

        // ---- gather with lane-contiguous columns (float4 at col 16f+4q) ----
        float mlo[32], mhi[32];
        const int tg_lo = tgs[r_lo], tg_hi = tgs[r_hi];
        float4 xi_lo[4];
        {
            if (tg_lo >= 0) {
                const float4* xi = (const float4*)(x + (size_t)tg_lo * HID) + q;
                const float4* xj = (const float4*)(x + (size_t)srs[r_lo] * HID) + q;
                float w = ews[r_lo];
                #pragma unroll
                for (int f = 0; f < 4; f++) {
                    float4 vi = __ldg(xi + 4 * f);
                    float4 vj = __ldg(xj + 4 * f);
                    xi_lo[f] = vi;
                    mlo[4*f+0] = vi.x; mlo[4*f+1] = vi.y; mlo[4*f+2] = vi.z; mlo[4*f+3] = vi.w;
                    mlo[16+4*f+0] = w * (vj.x - vi.x);
                    mlo[16+4*f+1] = w * (vj.y - vi.y);
                    mlo[16+4*f+2] = w * (vj.z - vi.z);
                    mlo[16+4*f+3] = w * (vj.w - vi.w);
                }
            } else {
                #pragma unroll
                for (int tt = 0; tt < 32; tt++) mlo[tt] = 0.0f;
                #pragma unroll
                for (int f = 0; f < 4; f++) xi_lo[f] = make_float4(0.f,0.f,0.f,0.f);
            }
        }
        {
            if (tg_hi >= 0) {
                const bool same = (tg_hi == tg_lo);
                const float4* xi = (const float4*)(x + (size_t)tg_hi * HID) + q;
                const float4* xj = (const float4*)(x + (size_t)srs[r_hi] * HID) + q;
                float w = ews[r_hi];
                #pragma unroll
                for (int f = 0; f < 4; f++) {
                    float4 vi = same ? xi_lo[f] : __ldg(xi + 4 * f);
                    float4 vj = __ldg(xj + 4 * f);
                    mhi[4*f+0] = vi.x; mhi[4*f+1] = vi.y; mhi[4*f+2] = vi.z; mhi[4*f+3] = vi.w;
                    mhi[16+4*f+0] = w * (vj.x - vi.x);
                    mhi[16+4*f+1] = w * (vj.y - vi.y);
                    mhi[16+4*f+2] = w * (vj.z - vi.z);
                    mhi[16+4*f+3] = w * (vj.w - vi.w);
                }
            } else {
                #pragma unroll
                for (int tt = 0; tt < 32; tt++) mhi[tt] = 0.0f;
            }
        }

        // ---- LN1 (width 128) in registers; keep fp32, pack to f16 in GEMM1 ----
        {
            float s_lo = 0.f, q_lo = 0.f, s_hi = 0.f, q_hi = 0.f;
            #pragma unroll
            for (int tt = 0; tt < 32; tt++) {
                s_lo += mlo[tt]; q_lo += mlo[tt] * mlo[tt];
                s_hi += mhi[tt]; q_hi += mhi[tt] * mhi[tt];
            }
            #pragma unroll
            for (int o = 1; o <= 2; o <<= 1) {
                s_lo += __shfl_xor_sync(0xffffffffu, s_lo, o);
                q_lo += __shfl_xor_sync(0xffffffffu, q_lo, o);
                s_hi += __shfl_xor_sync(0xffffffffu, s_hi, o);
                q_hi += __shfl_xor_sync(0xffffffffu, q_hi, o);
            }
            float mu_lo = s_lo * (1.0f / 128.0f);
            float mu_hi = s_hi * (1.0f / 128.0f);
            float r_l   = rsqrtf(fmaxf(q_lo * (1.0f / 128.0f) - mu_lo * mu_lo, 0.0f) + EPSF);
            float r_h   = rsqrtf(fmaxf(q_hi * (1.0f / 128.0f) - mu_hi * mu_hi, 0.0f) + EPSF);
            #pragma unroll
            for (int kt = 0; kt < 8; kt++) {
                int c0 = 16 * kt + 4 * q;
                #pragma unroll
                for (int j = 0; j < 4; j++) {
                    float g = g1s[c0 + j], b = b1s[c0 + j];
                    float h0 = (mlo[4*kt+j] - mu_lo) * r_l * g + b;
                    float h1 = (mhi[4*kt+j] - mu_hi) * r_h * g + b;
                    mlo[4*kt+j] = h0 > 0.f ? h0 : SLOPEF * h0;
                    mhi[4*kt+j] = h1 > 0.f ? h1 : SLOPEF * h1;
                }
            }
        }

        float acc[8][4];

        // ===== GEMM1: K=128, 8 fp16 MMA steps; B via paired LDS.128 =====
        #pragma unroll
        for (int nt = 0; nt < 8; nt++)
            #pragma unroll
            for (int j = 0; j < 4; j++) acc[nt][j] = 0.0f;
        #pragma unroll
        for (int kt = 0; kt < 8; kt++) {
            uint32_t a0 = hf2(mlo[4*kt+1], mlo[4*kt]);
            uint32_t a1 = hf2(mhi[4*kt+1], mhi[4*kt]);
            uint32_t a2 = hf2(mlo[4*kt+3], mlo[4*kt+2]);
            uint32_t a3 = hf2(mhi[4*kt+3], mhi[4*kt+2]);
            const uint4* wrow = w1p4 + (kt * 4 + q) * WP4 + grp;
            #pragma unroll
            for (int p = 0; p < 4; p++) {
                uint4 b4 = wrow[p * 8];
                mma_f16(acc[2*p],   a0, a1, a2, a3, b4.x, b4.y);
                mma_f16(acc[2*p+1], a0, a1, a2, a3, b4.z, b4.w);
            }
        }

        // ---- LN2 -> AB (pair-indexed f16x2) ----
        {
            float s_lo = 0.f, q_lo = 0.f, s_hi = 0.f, q_hi = 0.f;
            #pragma unroll
            for (int nt = 0; nt < 8; nt++) {
                s_lo += acc[nt][0] + acc[nt][1];
                q_lo += acc[nt][0]*acc[nt][0] + acc[nt][1]*acc[nt][1];
                s_hi += acc[nt][2] + acc[nt][3];
                q_hi += acc[nt][2]*acc[nt][2] + acc[nt][3]*acc[nt][3];
            }
            #pragma unroll
            for (int o = 1; o <= 2; o <<= 1) {
                s_lo += __shfl_xor_sync(0xffffffffu, s_lo, o);
                q_lo += __shfl_xor_sync(0xffffffffu, q_lo, o);
                s_hi += __shfl_xor_sync(0xffffffffu, s_hi, o);
                q_hi += __shfl_xor_sync(0xffffffffu, q_hi, o);
            }
            float mu_lo = s_lo * (1.0f/64.0f);
            float mu_hi = s_hi * (1.0f/64.0f);
            float r_l   = rsqrtf(fmaxf(q_lo * (1.0f/64.0f) - mu_lo*mu_lo, 0.0f) + EPSF);
            float r_h   = rsqrtf(fmaxf(q_hi * (1.0f/64.0f) - mu_hi*mu_hi, 0.0f) + EPSF);

            #pragma unroll
            for (int nt = 0; nt < 8; nt++) {
                int c0 = nt * 8 + 2 * q;
                float2 g = *(float2*)(g2s + c0);
                float2 b = *(float2*)(b2s + c0);
                float h0 = (acc[nt][0] - mu_lo) * r_l * g.x + b.x;
                float h1 = (acc[nt][1] - mu_lo) * r_l * g.y + b.y;
                float h2 = (acc[nt][2] - mu_hi) * r_h * g.x + b.x;
                float h3 = (acc[nt][3] - mu_hi) * r_h * g.y + b.y;
                h0 = h0 > 0.f ? h0 : SLOPEF * h0;
                h1 = h1 > 0.f ? h1 : SLOPEF * h1;
                h2 = h2 > 0.f ? h2 : SLOPEF * h2;
                h3 = h3 > 0.f ? h3 : SLOPEF * h3;
                AB[rp * APS2 + 4 * nt + q] = make_uint2(hf2(h1, h0), hf2(h3, h2));
            }
        }
        __syncwarp();

        // ===== GEMM2: K=64, 4 steps; A = LDS.128, B paired =====
        #pragma unroll
        for (int nt = 0; nt < 8; nt++)
            #pragma unroll
            for (int j = 0; j < 4; j++) acc[nt][j] = 0.0f;
        {
            const uint2* Ab = AB + rp * APS2;
            #pragma unroll
            for (int kt = 0; kt < 4; kt++) {
                uint4 av = *(const uint4*)(Ab + 8 * kt + 2 * q);
                const uint4* wrow = w2p4 + (kt * 4 + q) * WP4 + grp;
                #pragma unroll
                for (int p = 0; p < 4; p++) {
                    uint4 b4 = wrow[p * 8];
                    mma_f16(acc[2*p],   av.x, av.y, av.z, av.w, b4.x, b4.y);
                    mma_f16(acc[2*p+1], av.x, av.y, av.z, av.w, b4.z, b4.w);
                }
            }
        }
        __syncwarp();

        // ---- LN3 -> AB ----
        {
            float s_lo = 0.f, q_lo = 0.f, s_hi = 0.f, q_hi = 0.f;
            #pragma unroll
            for (int nt = 0; nt < 8; nt++) {
                s_lo += acc[nt][0] + acc[nt][1];
                q_lo += acc[nt][0]*acc[nt][0] + acc[nt][1]*acc[nt][1];
                s_hi += acc[nt][2] + acc[nt][3];
                q_hi += acc[nt][2]*acc[nt][2] + acc[nt][3]*acc[nt][3];
            }
            #pragma unroll
            for (int o = 1; o <= 2; o <<= 1) {
                s_lo += __shfl_xor_sync(0xffffffffu, s_lo, o);
                q_lo += __shfl_xor_sync(0xffffffffu, q_lo, o);
                s_hi += __shfl_xor_sync(0xffffffffu, s_hi, o);
                q_hi += __shfl_xor_sync(0xffffffffu, q_hi, o);
            }
            float mu_lo = s_lo * (1.0f/64.0f);
            float mu_hi = s_hi * (1.0f/64.0f);
            float r_l   = rsqrtf(fmaxf(q_lo * (1.0f/64.0f) - mu_lo*mu_lo, 0.0f) + EPSF);
            float r_h   = rsqrtf(fmaxf(q_hi * (1.0f/64.0f) - mu_hi*mu_hi, 0.0f) + EPSF);

            #pragma unroll
            for (int nt = 0; nt < 8; nt++) {
                int c0 = nt * 8 + 2 * q;
                float2 g = *(float2*)(g3s + c0);
                float2 b = *(float2*)(b3s + c0);
                float h0 = (acc[nt][0] - mu_lo) * r_l * g.x + b.x;
                float h1 = (acc[nt][1] - mu_lo) * r_l * g.y + b.y;
                float h2 = (acc[nt][2] - mu_hi) * r_h * g.x + b.x;
                float h3 = (acc[nt][3] - mu_hi) * r_h * g.y + b.y;
                h0 = h0 > 0.f ? h0 : SLOPEF * h0;
                h1 = h1 > 0.f ? h1 : SLOPEF * h1;
                h2 = h2 > 0.f ? h2 : SLOPEF * h2;
                h3 = h3 > 0.f ? h3 : SLOPEF * h3;
                AB[rp * APS2 + 4 * nt + q] = make_uint2(hf2(h1, h0), hf2(h3, h2));
            }
        }
        __syncwarp();

        // ===== GEMM3 =====
        #pragma unroll
        for (int nt = 0; nt < 8; nt++)
            #pragma unroll
            for (int j = 0; j < 4; j++) acc[nt][j] = 0.0f;
        {
            const uint2* Ab = AB + rp * APS2;
            #pragma unroll
            for (int kt = 0; kt < 4; kt++) {
                uint4 av = *(const uint4*)(Ab + 8 * kt + 2 * q);
                const uint4* wrow = w3p4 + (kt * 4 + q) * WP4 + grp;
                #pragma unroll
                for (int p = 0; p < 4; p++) {
                    uint4 b4 = wrow[p * 8];
                    mma_f16(acc[2*p],   av.x, av.y, av.z, av.w, b4.x, b4.y);
                    mma_f16(acc[2*p+1], av.x, av.y, av.z, av.w, b4.z, b4.w);
                }
            }
        }
        __syncwarp();

        // ---- epilogue: fast path (single target in warp's 16 rows) or f16 MS staging ----
        {
            unsigned* outu = (unsigned*)out;
            const int rs = wid * 16;
            const int t0 = tgs[rs];
            if (t0 >= 0 && tgs[rs + 15] == t0) {
                // all 16 rows same target (tgs monotone within tile)
                #pragma unroll
                for (int nt = 0; nt < 8; nt++) {
                    float v0 = fmaxf(acc[nt][0], acc[nt][2]);
                    float v1 = fmaxf(acc[nt][1], acc[nt][3]);
                    #pragma unroll
                    for (int o = 4; o <= 16; o <<= 1) {
                        v0 = fmaxf(v0, __shfl_xor_sync(0xffffffffu, v0, o));
                        v1 = fmaxf(v1, __shfl_xor_sync(0xffffffffu, v1, o));
                    }
                    if (grp == 0) {
                        unsigned base = (unsigned)t0 * HID + nt * 8 + 2 * q;
                        atomicMax(outu + base,     fkey(v0));
                        atomicMax(outu + base + 1, fkey(v1));
                    }
                }
            } else {
                // slow path: stage f16x2 messages, run-aggregated sweep
                #pragma unroll
                for (int nt = 0; nt < 8; nt++) {
                    int cp = 4 * nt + q;
                    MS16[r_lo * MS4 + cp] = hf2(acc[nt][1], acc[nt][0]);
                    MS16[r_hi * MS4 + cp] = hf2(acc[nt][3], acc[nt][2]);
                }
                __syncwarp();
                const int cp = lane;   // column pair 0..31 -> cols 2cp, 2cp+1
                float m0 = NEG_INF_F, m1 = NEG_INF_F;
                int cur = tgs[rs];
                #pragma unroll 4
                for (int r = rs; r < rs + 16; r++) {
                    int tg2 = tgs[r];
                    if (tg2 != cur) {
                        if (cur >= 0) {
                            unsigned base = (unsigned)cur * HID + 2 * cp;
                            atomicMax(outu + base,     fkey(m0));
                            atomicMax(outu + base + 1, fkey(m1));
                        }
                        cur = tg2;
                        m0 = NEG_INF_F; m1 = NEG_INF_F;
                    }
                    uint32_t v = MS16[r * MS4 + cp];
                    __half2 h2v = *reinterpret_cast<__half2*>(&v);
                    m0 = fmaxf(m0, __low2float(h2v));
                    m1 = fmaxf(m1, __high2float(h2v));
                }
                if (cur >= 0) {
                    unsigned base = (unsigned)cur * HID + 2 * cp;
                    atomicMax(outu + base,     fkey(m0));
                    atomicMax(outu + base + 1, fkey(m1));
                }
            }
        }
    }
    #undef LOAD_META
}

extern "C" void kernel_launch(void* const* d_in, const int* in_sizes, int n_in,
                              void* d_out, int out_size) {
    const float* x  = (const float*)d_in[0];
    const float* ew = (const float*)d_in[1];
    const int*   ei = (const int*)d_in[2];
    const float* w1 = (const float*)d_in[3];
    const float* w2 = (const float*)d_in[4];
    const float* w3 = (const float*)d_in[5];
    const float* g1 = (const float*)d_in[6];
    const float* b1 = (const float*)d_in[7];
    const float* g2 = (const float*)d_in[8];
    const float* b2 = (const float*)d_in[9];
    const float* g3 = (const float*)d_in[10];
    const float* b3 = (const float*)d_in[11];
    float* out = (float*)d_out;

    const int E  = in_sizes[1];
    const int NH = out_size;
    const int N  = NH / HID;
    const int n  = N + 1;
    const int nchunk = (n + SCAN_CHUNK - 1) / SCAN_CHUNK;
    const int ntiles = (E + TILE - 1) / TILE;

    int nsm = 148;
    cudaDeviceGetAttribute(&nsm, cudaDevAttrMultiProcessorCount, 0);
    int nblocks = 2 * nsm;
    if (nblocks > ntiles) nblocks = ntiles;
    int ssblocks = 4 * nsm;

    cudaFuncSetAttribute(edge_kernel, cudaFuncAttributeMaxDynamicSharedMemorySize, SMEM_BYTES);

    int zi_n = (n > NH / 4) ? n : NH / 4;
    zero_init_kernel<<<(zi_n + 255) / 256, 256>>>(n, (uint4*)out, NH / 4);       // #1
    hist_kernel<<<(E + 255) / 256, 256>>>(ei, E);                                 // #2
    scan_scatter_kernel<<<ssblocks, 256>>>(ei, E, n, nchunk);                     // #3
    edge_kernel<<<nblocks, NTHR, SMEM_BYTES>>>(                                   // #4 (profiled)
        x, ew, ei, w1, w2, w3, g1, b1, g2, b2, g3, b3, out, E, ntiles);
    finalize_kernel<<<(NH + 255) / 256, 256>>>(x, out, NH);                       // #5
}